// round 11
// baseline (speedup 1.0000x reference)
#include <cuda_runtime.h>
#include <cuda_fp16.h>
#include <math.h>

#define N_NODES 100000
#define N_EDGES 1600000
#define HID 32
#define CSR_T 512

// ---------------- device scratch ----------------
__device__ float4 g_h  [N_NODES * 8];
__device__ float4 g_A  [N_NODES * 8];
__device__ unsigned long long g_Bh[N_NODES * 8];   // fp16 B table
__device__ float4 g_agg[N_NODES * 8];
__device__ float4 g_pos4[N_NODES];
__device__ int2   g_epack[N_EDGES];               // CSR by dst: (src, dist bits)
__device__ int2   g_tmp  [N_EDGES];               // decoded (src, dst)
// zero region: [0, N_NODES) = hist; [N_NODES] = barrier count; [N_NODES+1] = barrier gen
__device__ __align__(8) int g_zero[N_NODES + 2];
__device__ int    g_off [N_NODES];
__device__ int    g_cur [N_NODES];
__device__ int    g_part[512];

// folded matrices/vectors
__device__ float  c_Pa[3][1024], c_Pb[3][1024], c_P1[3][1024], c_P2[3][1024], c_Po[1024];
__device__ float  c_qa[3][32],  c_qb[3][32],  c_q1[3][32],  c_v[3][32],  c_qo[32];

// ---------------- helpers ----------------
__device__ __forceinline__ float4 fma4(float f, float4 w, float4 a) {
    a.x = fmaf(f, w.x, a.x); a.y = fmaf(f, w.y, a.y);
    a.z = fmaf(f, w.z, a.z); a.w = fmaf(f, w.w, a.w);
    return a;
}
__device__ __forceinline__ float4 add4(float4 a, float4 b) {
    a.x += b.x; a.y += b.y; a.z += b.z; a.w += b.w; return a;
}
__device__ __forceinline__ float4 relu4(float4 v) {
    v.x = fmaxf(v.x, 0.f); v.y = fmaxf(v.y, 0.f);
    v.z = fmaxf(v.z, 0.f); v.w = fmaxf(v.w, 0.f); return v;
}
#define COMP(v, c) ((c) == 0 ? (v).x : (c) == 1 ? (v).y : (c) == 2 ? (v).z : (v).w)

__device__ __forceinline__ ulonglong2 pack4(float4 v) {
    ulonglong2 r;
    asm("mov.b64 %0, {%1, %2};" : "=l"(r.x) : "f"(v.x), "f"(v.y));
    asm("mov.b64 %0, {%1, %2};" : "=l"(r.y) : "f"(v.z), "f"(v.w));
    return r;
}
__device__ __forceinline__ float4 unpack4(ulonglong2 v) {
    float4 r;
    asm("mov.b64 {%0, %1}, %2;" : "=f"(r.x), "=f"(r.y) : "l"(v.x));
    asm("mov.b64 {%0, %1}, %2;" : "=f"(r.z), "=f"(r.w) : "l"(v.y));
    return r;
}
__device__ __forceinline__ unsigned long long f4_to_h4(float4 v) {
    __half2 h0 = __floats2half2_rn(v.x, v.y);
    __half2 h1 = __floats2half2_rn(v.z, v.w);
    unsigned lo = *reinterpret_cast<unsigned*>(&h0);
    unsigned hi = *reinterpret_cast<unsigned*>(&h1);
    return (unsigned long long)lo | ((unsigned long long)hi << 32);
}
__device__ __forceinline__ float4 h4_to_f4(unsigned long long v) {
    unsigned lo = (unsigned)v, hi = (unsigned)(v >> 32);
    __half2 h0 = *reinterpret_cast<__half2*>(&lo);
    __half2 h1 = *reinterpret_cast<__half2*>(&hi);
    float2 f0 = __half22float2(h0), f1 = __half22float2(h1);
    return make_float4(f0.x, f0.y, f1.x, f1.y);
}

__device__ __forceinline__ void gemv32(const float4* __restrict__ sW,
                                       const float4* xr, ulonglong2* acc) {
#pragma unroll
    for (int k = 0; k < 32; k++) {
        float f = COMP(xr[k >> 2], k & 3);
        unsigned long long f2;
        asm("mov.b64 %0, {%1, %1};" : "=l"(f2) : "f"(f));
        const ulonglong2* w = (const ulonglong2*)(sW + k * 8);
#pragma unroll
        for (int i = 0; i < 8; i++) {
            ulonglong2 wv = w[i];
            asm("fma.rn.f32x2 %0, %1, %2, %0;" : "+l"(acc[i].x) : "l"(f2), "l"(wv.x));
            asm("fma.rn.f32x2 %0, %1, %2, %0;" : "+l"(acc[i].y) : "l"(f2), "l"(wv.y));
        }
    }
}

// ---------------- software grid barrier (all blocks co-resident by construction) ----------------
__device__ __forceinline__ void gbar(int nb) {
    __syncthreads();
    if (threadIdx.x == 0) {
        int* cnt = &g_zero[N_NODES];
        int* gen = &g_zero[N_NODES + 1];
        int g = atomicAdd(gen, 0);
        __threadfence();
        if (atomicAdd(cnt, 1) == nb - 1) {
            *cnt = 0;                      // all arrived; only releaser writes
            __threadfence();
            atomicExch(gen, g + 1);
        } else {
            while (atomicAdd(gen, 0) == g) { __nanosleep(64); }
        }
        __threadfence();
    }
    __syncthreads();
}

// ---------------- persistent CSR build: decode+hist -> scan -> scatter ----------------
__global__ void __launch_bounds__(CSR_T) csr_kernel(const void* ei, const float* __restrict__ pos) {
    __shared__ int s_i64;
    __shared__ int s_scan[CSR_T];
    int t = threadIdx.x;
    int b = blockIdx.x;
    int nb = gridDim.x;
    int gtid = b * CSR_T + t;
    int gsz = nb * CSR_T;

    if (t < 32) {
        // int64 edge values < 1e5 -> odd 32-bit words all zero; int32 -> random nonzero
        int v = ((const int*)ei)[2 * t + 1];
        unsigned m = __ballot_sync(0xffffffffu, v != 0);
        if (t == 0) s_i64 = (m == 0);
    }
    __syncthreads();
    int i64 = s_i64;

    // phase 1: pos pack + decode stash + dst histogram
    for (int n = gtid; n < N_NODES; n += gsz)
        g_pos4[n] = make_float4(pos[n * 3 + 0], pos[n * 3 + 1], pos[n * 3 + 2], 0.f);
    for (int e = gtid; e < N_EDGES; e += gsz) {
        int src, dst;
        if (i64) {
            const long long* p = (const long long*)ei;
            src = (int)p[e]; dst = (int)p[N_EDGES + e];
        } else {
            const int* p = (const int*)ei;
            src = p[e]; dst = p[N_EDGES + e];
        }
        g_tmp[e] = make_int2(src, dst);
        atomicAdd(&g_zero[dst], 1);
    }
    gbar(nb);

    // phase 2: block-local scan over chunk of CH nodes (2 sequential items per thread)
    int CH = (((N_NODES + nb - 1) / nb) + 1) & ~1;   // even, <= 1024 for nb >= 98
    int base = b * CH;
    int idx0 = base + 2 * t;
    int idx1 = idx0 + 1;
    int lim = min(base + CH, N_NODES);
    int v0 = (idx0 < lim) ? g_zero[idx0] : 0;
    int v1 = (idx1 < lim) ? g_zero[idx1] : 0;
    int pairsum = v0 + v1;
    s_scan[t] = pairsum;
    __syncthreads();
#pragma unroll
    for (int off = 1; off < CSR_T; off <<= 1) {
        int tt = (t >= off) ? s_scan[t - off] : 0;
        __syncthreads();
        s_scan[t] += tt;
        __syncthreads();
    }
    int texcl = s_scan[t] - pairsum;
    if (t == CSR_T - 1) g_part[b] = s_scan[CSR_T - 1];
    gbar(nb);

    // phase 3: block 0 scans block partials (exclusive), nb <= 512
    if (b == 0) {
        int pv = (t < nb) ? g_part[t] : 0;
        s_scan[t] = pv;
        __syncthreads();
#pragma unroll
        for (int off = 1; off < CSR_T; off <<= 1) {
            int tt = (t >= off) ? s_scan[t - off] : 0;
            __syncthreads();
            s_scan[t] += tt;
            __syncthreads();
        }
        if (t < nb) g_part[t] = s_scan[t] - pv;
    }
    gbar(nb);

    // phase 4: write offsets + cursors
    {
        int pbase = g_part[b];
        if (idx0 < lim) { int o = pbase + texcl;      g_off[idx0] = o; g_cur[idx0] = o; }
        if (idx1 < lim) { int o = pbase + texcl + v0; g_off[idx1] = o; g_cur[idx1] = o; }
    }
    gbar(nb);

    // phase 5: scatter edges into CSR order (by dst)
    for (int e = gtid; e < N_EDGES; e += gsz) {
        int2 sd = g_tmp[e];
        float4 pd = __ldg(&g_pos4[sd.y]);
        float4 ps = __ldg(&g_pos4[sd.x]);
        float dx = pd.x - ps.x, dy = pd.y - ps.y, dz = pd.z - ps.z;
        float dist = sqrtf(dx * dx + dy * dy + dz * dz);
        int p = atomicAdd(&g_cur[sd.y], 1);
        g_epack[p] = make_int2(sd.x, __float_as_int(dist));
    }
}

// ---------------- precompute folded matrices ----------------
__global__ void __launch_bounds__(256) precompute_kernel(
    const float* __restrict__ enc_w2, const float* __restrict__ enc_b2,
    const float* __restrict__ msg_w1, const float* __restrict__ msg_b1,
    const float* __restrict__ msg_w2, const float* __restrict__ msg_b2,
    const float* __restrict__ upd_w1, const float* __restrict__ upd_b1,
    const float* __restrict__ upd_w2, const float* __restrict__ upd_b2,
    const float* __restrict__ out_w, const float* __restrict__ out_b) {
    int b = blockIdx.x;
    int t = threadIdx.x;
    if (b < 13) {
        int l = (b < 12) ? (b % 3) : 2;
        int kind = (b < 12) ? (b / 3) : 4;
        const float* Wp = (l == 0) ? enc_w2 : upd_w2 + (size_t)(l - 1) * 1024;
        const float* L; const float* R; float* P;
        switch (kind) {
            case 0: L = Wp;                      R = msg_w1 + (size_t)l * 2080;        P = c_Pa[l]; break;
            case 1: L = Wp;                      R = msg_w1 + (size_t)l * 2080 + 1024; P = c_Pb[l]; break;
            case 2: L = Wp;                      R = upd_w1 + (size_t)l * 2048;        P = c_P1[l]; break;
            case 3: L = msg_w2 + (size_t)l*1024; R = upd_w1 + (size_t)l * 2048 + 1024; P = c_P2[l]; break;
            default: L = upd_w2 + 2048;          R = out_w;                            P = c_Po;    break;
        }
        for (int e = t; e < 1024; e += 256) {
            int i = e >> 5, j = e & 31;
            float s = 0.f;
            for (int k = 0; k < 32; k++) s = fmaf(L[i * 32 + k], R[k * 32 + j], s);
            P[e] = s;
        }
    } else {
        for (int e = t; e < 416; e += 256) {
            int vid = e >> 5, j = e & 31;
            int l = vid % 3;
            const float* cp = (l == 0) ? enc_b2 : upd_b2 + (size_t)(l - 1) * 32;
            float s = 0.f;
            if (vid < 3) {
                const float* R = msg_w1 + (size_t)l * 2080;
                for (int k = 0; k < 32; k++) s = fmaf(cp[k], R[k * 32 + j], s);
                c_qa[l][j] = s;
            } else if (vid < 6) {
                const float* R = msg_w1 + (size_t)l * 2080 + 1024;
                for (int k = 0; k < 32; k++) s = fmaf(cp[k], R[k * 32 + j], s);
                c_qb[l][j] = s;
            } else if (vid < 9) {
                const float* R = upd_w1 + (size_t)l * 2048;
                for (int k = 0; k < 32; k++) s = fmaf(cp[k], R[k * 32 + j], s);
                c_q1[l][j] = s + upd_b1[l * 32 + j];
            } else if (vid < 12) {
                const float* R = upd_w1 + (size_t)l * 2048 + 1024;
                const float* mb = msg_b2 + (size_t)l * 32;
                for (int k = 0; k < 32; k++) s = fmaf(mb[k], R[k * 32 + j], s);
                c_v[l][j] = s;
            } else {
                const float* ub = upd_b2 + 2 * 32;
                for (int k = 0; k < 32; k++) s = fmaf(ub[k], out_w[k * 32 + j], s);
                c_qo[j] = s + out_b[j];
            }
        }
    }
}

// ---------------- encoder: h = relu(feat@w1+b1); A=h@Pa0+qa0; B=h@Pb0+qb0 ----------------
__global__ void __launch_bounds__(128) encoder_kernel(
    const float* __restrict__ feat,
    const float* __restrict__ w1, const float* __restrict__ b1) {
    __shared__ float  s_feat[128 * 33];
    __shared__ float4 s_w1[64 * 8];
    __shared__ float4 s_pa[256], s_pb[256];
    __shared__ float4 s_b1[8], s_qa[8], s_qb[8];
    for (int i = threadIdx.x; i < 512; i += 128) s_w1[i] = ((const float4*)w1)[i];
    for (int i = threadIdx.x; i < 256; i += 128) {
        s_pa[i] = ((const float4*)c_Pa[0])[i];
        s_pb[i] = ((const float4*)c_Pb[0])[i];
    }
    if (threadIdx.x < 8) {
        s_b1[threadIdx.x] = ((const float4*)b1)[threadIdx.x];
        s_qa[threadIdx.x] = ((const float4*)c_qa[0])[threadIdx.x];
        s_qb[threadIdx.x] = ((const float4*)c_qb[0])[threadIdx.x];
    }
    __syncthreads();
    int base = blockIdx.x * 128;
    int n = base + threadIdx.x;
    bool act = (n < N_NODES);

    ulonglong2 hacc[8];
#pragma unroll
    for (int i = 0; i < 8; i++) hacc[i] = pack4(s_b1[i]);

#pragma unroll
    for (int half = 0; half < 2; half++) {
        for (int j = threadIdx.x; j < 128 * 32; j += 128) {
            int r = j >> 5, col = j & 31;
            int nn = base + r;
            s_feat[r * 33 + col] =
                (nn < N_NODES) ? feat[(size_t)nn * 64 + half * 32 + col] : 0.f;
        }
        __syncthreads();
        const float* frow = &s_feat[threadIdx.x * 33];
#pragma unroll 8
        for (int k = 0; k < 32; k++) {
            float f = frow[k];
            unsigned long long f2;
            asm("mov.b64 %0, {%1, %1};" : "=l"(f2) : "f"(f));
            const ulonglong2* w = (const ulonglong2*)(s_w1 + (half * 32 + k) * 8);
#pragma unroll
            for (int i = 0; i < 8; i++) {
                ulonglong2 wv = w[i];
                asm("fma.rn.f32x2 %0, %1, %2, %0;" : "+l"(hacc[i].x) : "l"(f2), "l"(wv.x));
                asm("fma.rn.f32x2 %0, %1, %2, %0;" : "+l"(hacc[i].y) : "l"(f2), "l"(wv.y));
            }
        }
        __syncthreads();
    }
    float4 h[8];
#pragma unroll
    for (int i = 0; i < 8; i++) h[i] = relu4(unpack4(hacc[i]));

    ulonglong2 a[8], b[8];
#pragma unroll
    for (int i = 0; i < 8; i++) { a[i] = pack4(s_qa[i]); b[i] = pack4(s_qb[i]); }
    gemv32(s_pa, h, a);
    gemv32(s_pb, h, b);

    if (act) {
        ulonglong2* ph = (ulonglong2*)&g_h[(size_t)n * 8];
        ulonglong2* pa = (ulonglong2*)&g_A[(size_t)n * 8];
#pragma unroll
        for (int i = 0; i < 8; i++) {
            ph[i] = pack4(h[i]);
            pa[i] = a[i];
            g_Bh[(size_t)n * 8 + i] = f4_to_h4(unpack4(b[i]));
        }
    }
}

// ---------------- per layer: agg[n] = sum_e relu(A[n] + B[src_e] + d_e*c + b1) ----------------
// 8 lanes per node (comp c = lane&7), 4 nodes per warp (group g = lane>>3).
// Each lane accumulates its component across its node's CSR edge list; no shuffles.
__global__ void __launch_bounds__(256) agg_kernel(
    const float* __restrict__ w1c, const float* __restrict__ b1) {
    int warp = (blockIdx.x * 256 + threadIdx.x) >> 5;
    int lane = threadIdx.x & 31;
    int c = lane & 7;
    int g = lane >> 3;
    int n = warp * 4 + g;
    bool act = (n < N_NODES);

    float4 cv = __ldg(((const float4*)w1c) + c);
    float4 bb = __ldg(((const float4*)b1) + c);

    int start = 0, deg = 0;
    if (act) {
        start = __ldg(&g_off[n]);
        deg   = __ldg(&g_zero[n]);   // hist
    }
    float4 ab = make_float4(0.f, 0.f, 0.f, 0.f);
    if (act) ab = add4(g_A[(size_t)n * 8 + c], bb);

    float4 acc0 = make_float4(0.f, 0.f, 0.f, 0.f);
    float4 acc1 = make_float4(0.f, 0.f, 0.f, 0.f);
    int i = 0;
    for (; i + 1 < deg; i += 2) {
        int2 sd0 = __ldg(&g_epack[start + i]);
        int2 sd1 = __ldg(&g_epack[start + i + 1]);
        float4 b0 = h4_to_f4(__ldg(&g_Bh[(size_t)sd0.x * 8 + c]));
        float4 b1v = h4_to_f4(__ldg(&g_Bh[(size_t)sd1.x * 8 + c]));
        acc0 = add4(acc0, relu4(fma4(__int_as_float(sd0.y), cv, add4(ab, b0))));
        acc1 = add4(acc1, relu4(fma4(__int_as_float(sd1.y), cv, add4(ab, b1v))));
    }
    if (i < deg) {
        int2 sd = __ldg(&g_epack[start + i]);
        float4 b = h4_to_f4(__ldg(&g_Bh[(size_t)sd.x * 8 + c]));
        acc0 = add4(acc0, relu4(fma4(__int_as_float(sd.y), cv, add4(ab, b))));
    }
    if (act) g_agg[(size_t)n * 8 + c] = add4(acc0, acc1);
}

// ---------------- per layer update (folded) ----------------
__global__ void __launch_bounds__(128) update_kernel(int l, int last, float* __restrict__ outp) {
    __shared__ float4 s_p1[256], s_p2[256], s_pc[256], s_pd[256];
    __shared__ float4 s_q1[8], s_v[8], s_qc[8], s_qd[8];
    {
        const float* P1 = c_P1[l];
        const float* P2 = c_P2[l];
        const float* Pc = last ? c_Po : c_Pa[l + 1 < 3 ? l + 1 : 0];
        const float* Pd = last ? c_Po : c_Pb[l + 1 < 3 ? l + 1 : 0];
        for (int i = threadIdx.x; i < 256; i += 128) {
            s_p1[i] = ((const float4*)P1)[i];
            s_p2[i] = ((const float4*)P2)[i];
            s_pc[i] = ((const float4*)Pc)[i];
            s_pd[i] = ((const float4*)Pd)[i];
        }
        if (threadIdx.x < 8) {
            s_q1[threadIdx.x] = ((const float4*)c_q1[l])[threadIdx.x];
            s_v[threadIdx.x]  = ((const float4*)c_v[l])[threadIdx.x];
            const float* qc = last ? c_qo : c_qa[l + 1 < 3 ? l + 1 : 0];
            const float* qd = last ? c_qo : c_qb[l + 1 < 3 ? l + 1 : 0];
            s_qc[threadIdx.x] = ((const float4*)qc)[threadIdx.x];
            s_qd[threadIdx.x] = ((const float4*)qd)[threadIdx.x];
        }
    }
    __syncthreads();
    int n = blockIdx.x * blockDim.x + threadIdx.x;
    if (n >= N_NODES) return;

    float deg = (float)g_zero[n];
    ulonglong2 uacc[8];
#pragma unroll
    for (int i = 0; i < 8; i++) {
        float4 q = s_q1[i], vv = s_v[i];
        uacc[i] = pack4(make_float4(fmaf(deg, vv.x, q.x), fmaf(deg, vv.y, q.y),
                                    fmaf(deg, vv.z, q.z), fmaf(deg, vv.w, q.w)));
    }
    float4 hr[8];
#pragma unroll
    for (int i = 0; i < 8; i++) hr[i] = g_h[(size_t)n * 8 + i];
    gemv32(s_p1, hr, uacc);
    float4 ar[8];
#pragma unroll
    for (int i = 0; i < 8; i++) ar[i] = g_agg[(size_t)n * 8 + i];
    gemv32(s_p2, ar, uacc);

    float4 u[8];
#pragma unroll
    for (int i = 0; i < 8; i++) u[i] = relu4(unpack4(uacc[i]));

    ulonglong2 cacc[8];
#pragma unroll
    for (int i = 0; i < 8; i++) cacc[i] = pack4(s_qc[i]);
    gemv32(s_pc, u, cacc);

    if (!last) {
        ulonglong2 dacc[8];
#pragma unroll
        for (int i = 0; i < 8; i++) dacc[i] = pack4(s_qd[i]);
        gemv32(s_pd, u, dacc);
        ulonglong2* ph = (ulonglong2*)&g_h[(size_t)n * 8];
        ulonglong2* pa = (ulonglong2*)&g_A[(size_t)n * 8];
#pragma unroll
        for (int i = 0; i < 8; i++) {
            ph[i] = pack4(u[i]);
            pa[i] = cacc[i];
            g_Bh[(size_t)n * 8 + i] = f4_to_h4(unpack4(dacc[i]));
        }
    } else {
        ulonglong2* orow = (ulonglong2*)(outp + (size_t)n * 32);
#pragma unroll
        for (int i = 0; i < 8; i++) orow[i] = cacc[i];
    }
}

// ---------------- launch ----------------
extern "C" void kernel_launch(void* const* d_in, const int* in_sizes, int n_in,
                              void* d_out, int out_size) {
    const float* node_feat = (const float*)d_in[0];
    const float* pos       = (const float*)d_in[1];
    const void*  ei        = d_in[2];
    const float* enc_w1    = (const float*)d_in[3];
    const float* enc_b1    = (const float*)d_in[4];
    const float* enc_w2    = (const float*)d_in[5];
    const float* enc_b2    = (const float*)d_in[6];
    const float* msg_w1    = (const float*)d_in[7];
    const float* msg_b1    = (const float*)d_in[8];
    const float* msg_w2    = (const float*)d_in[9];
    const float* msg_b2    = (const float*)d_in[10];
    const float* upd_w1    = (const float*)d_in[11];
    const float* upd_b1    = (const float*)d_in[12];
    const float* upd_w2    = (const float*)d_in[13];
    const float* upd_b2    = (const float*)d_in[14];
    const float* out_w     = (const float*)d_in[15];
    const float* out_b     = (const float*)d_in[16];
    float* out = (float*)d_out;

    const int NODE_BLOCKS = (N_NODES + 127) / 128;
    const int AGG_BLOCKS  = (((N_NODES + 3) / 4) * 32 + 255) / 256;

    // size persistent CSR grid so ALL blocks are co-resident (grid barrier safety)
    int nsm = 0, occ = 0;
    cudaDeviceGetAttribute(&nsm, cudaDevAttrMultiProcessorCount, 0);
    cudaOccupancyMaxActiveBlocksPerMultiprocessor(&occ, csr_kernel, CSR_T, 0);
    if (occ < 1) occ = 1;
    int csr_blocks = occ * nsm;
    if (csr_blocks > 512) csr_blocks = 512;
    if (csr_blocks > 148 * 3) csr_blocks = 148 * 3;   // conservative cap

    cudaStream_t s1;
    cudaStreamCreateWithFlags(&s1, cudaStreamNonBlocking);
    cudaEvent_t ev_fork, ev_join;
    cudaEventCreateWithFlags(&ev_fork, cudaEventDisableTiming);
    cudaEventCreateWithFlags(&ev_join, cudaEventDisableTiming);

    // fork
    cudaEventRecord(ev_fork, 0);
    cudaStreamWaitEvent(s1, ev_fork, 0);

    // ---- chain A (capture stream): memset -> persistent CSR build ----
    void* p_zero = nullptr;
    cudaGetSymbolAddress(&p_zero, g_zero);
    cudaMemsetAsync(p_zero, 0, (N_NODES + 2) * sizeof(int), 0);
    csr_kernel<<<csr_blocks, CSR_T>>>(ei, pos);                        // kernel #1

    // ---- chain B (stream s1): precompute -> encoder ----
    precompute_kernel<<<14, 256, 0, s1>>>(enc_w2, enc_b2, msg_w1, msg_b1, msg_w2, msg_b2,
                                          upd_w1, upd_b1, upd_w2, upd_b2, out_w, out_b); // #2
    encoder_kernel<<<NODE_BLOCKS, 128, 0, s1>>>(node_feat, enc_w1, enc_b1);              // #3
    cudaEventRecord(ev_join, s1);

    // join
    cudaStreamWaitEvent(0, ev_join, 0);

    for (int l = 0; l < 3; l++) {
        const float* w1 = msg_w1 + (size_t)l * 65 * 32;
        agg_kernel<<<AGG_BLOCKS, 256>>>(w1 + 64 * 32, msg_b1 + (size_t)l * 32);  // l=0 -> kernel #4 (profiled)
        update_kernel<<<NODE_BLOCKS, 128>>>(l, l == 2, out);
    }
}

// round 12
// speedup vs baseline: 1.0021x; 1.0021x over previous
#include <cuda_runtime.h>
#include <cuda_fp16.h>
#include <math.h>

#define N_NODES 100000
#define N_EDGES 1600000
#define HID 32
#define CSR_T 512

// ---------------- device scratch ----------------
__device__ float4 g_h  [N_NODES * 8];
__device__ float4 g_A  [N_NODES * 8];
__device__ unsigned long long g_Bh[N_NODES * 8];   // fp16 B table
__device__ float4 g_agg[N_NODES * 8];
__device__ float4 g_pos4[N_NODES];
__device__ int2   g_epack[N_EDGES];               // CSR by dst: (src*8, dist as half2)
__device__ int2   g_tmp  [N_EDGES];               // decoded (src, dst)
// zero region: [0, N_NODES) = hist; [N_NODES] = barrier count; [N_NODES+1] = barrier gen
__device__ __align__(8) int g_zero[N_NODES + 2];
__device__ int    g_off [N_NODES];
__device__ int    g_cur [N_NODES];
__device__ int    g_part[512];

// folded matrices/vectors
__device__ float  c_Pa[3][1024], c_Pb[3][1024], c_P1[3][1024], c_P2[3][1024], c_Po[1024];
__device__ float  c_qa[3][32],  c_qb[3][32],  c_q1[3][32],  c_v[3][32],  c_qo[32];

// ---------------- helpers ----------------
__device__ __forceinline__ float4 fma4(float f, float4 w, float4 a) {
    a.x = fmaf(f, w.x, a.x); a.y = fmaf(f, w.y, a.y);
    a.z = fmaf(f, w.z, a.z); a.w = fmaf(f, w.w, a.w);
    return a;
}
__device__ __forceinline__ float4 add4(float4 a, float4 b) {
    a.x += b.x; a.y += b.y; a.z += b.z; a.w += b.w; return a;
}
__device__ __forceinline__ float4 relu4(float4 v) {
    v.x = fmaxf(v.x, 0.f); v.y = fmaxf(v.y, 0.f);
    v.z = fmaxf(v.z, 0.f); v.w = fmaxf(v.w, 0.f); return v;
}
#define COMP(v, c) ((c) == 0 ? (v).x : (c) == 1 ? (v).y : (c) == 2 ? (v).z : (v).w)

__device__ __forceinline__ ulonglong2 pack4(float4 v) {
    ulonglong2 r;
    asm("mov.b64 %0, {%1, %2};" : "=l"(r.x) : "f"(v.x), "f"(v.y));
    asm("mov.b64 %0, {%1, %2};" : "=l"(r.y) : "f"(v.z), "f"(v.w));
    return r;
}
__device__ __forceinline__ float4 unpack4(ulonglong2 v) {
    float4 r;
    asm("mov.b64 {%0, %1}, %2;" : "=f"(r.x), "=f"(r.y) : "l"(v.x));
    asm("mov.b64 {%0, %1}, %2;" : "=f"(r.z), "=f"(r.w) : "l"(v.y));
    return r;
}
__device__ __forceinline__ unsigned long long f4_to_h4(float4 v) {
    __half2 h0 = __floats2half2_rn(v.x, v.y);
    __half2 h1 = __floats2half2_rn(v.z, v.w);
    unsigned lo = *reinterpret_cast<unsigned*>(&h0);
    unsigned hi = *reinterpret_cast<unsigned*>(&h1);
    return (unsigned long long)lo | ((unsigned long long)hi << 32);
}

__device__ __forceinline__ void gemv32(const float4* __restrict__ sW,
                                       const float4* xr, ulonglong2* acc) {
#pragma unroll
    for (int k = 0; k < 32; k++) {
        float f = COMP(xr[k >> 2], k & 3);
        unsigned long long f2;
        asm("mov.b64 %0, {%1, %1};" : "=l"(f2) : "f"(f));
        const ulonglong2* w = (const ulonglong2*)(sW + k * 8);
#pragma unroll
        for (int i = 0; i < 8; i++) {
            ulonglong2 wv = w[i];
            asm("fma.rn.f32x2 %0, %1, %2, %0;" : "+l"(acc[i].x) : "l"(f2), "l"(wv.x));
            asm("fma.rn.f32x2 %0, %1, %2, %0;" : "+l"(acc[i].y) : "l"(f2), "l"(wv.y));
        }
    }
}

// ---------------- software grid barrier (all blocks co-resident by construction) ----------------
__device__ __forceinline__ void gbar(int nb) {
    __syncthreads();
    if (threadIdx.x == 0) {
        int* cnt = &g_zero[N_NODES];
        int* gen = &g_zero[N_NODES + 1];
        int g = atomicAdd(gen, 0);
        __threadfence();
        if (atomicAdd(cnt, 1) == nb - 1) {
            *cnt = 0;
            __threadfence();
            atomicExch(gen, g + 1);
        } else {
            while (atomicAdd(gen, 0) == g) { __nanosleep(64); }
        }
        __threadfence();
    }
    __syncthreads();
}

// ---------------- persistent CSR build: decode+hist -> scan -> scatter ----------------
__global__ void __launch_bounds__(CSR_T) csr_kernel(const void* ei, const float* __restrict__ pos) {
    __shared__ int s_i64;
    __shared__ int s_scan[CSR_T];
    int t = threadIdx.x;
    int b = blockIdx.x;
    int nb = gridDim.x;
    int gtid = b * CSR_T + t;
    int gsz = nb * CSR_T;

    if (t < 32) {
        // int64 edge values < 1e5 -> odd 32-bit words all zero; int32 -> random nonzero
        int v = ((const int*)ei)[2 * t + 1];
        unsigned m = __ballot_sync(0xffffffffu, v != 0);
        if (t == 0) s_i64 = (m == 0);
    }
    __syncthreads();
    int i64 = s_i64;

    // phase 1: pos pack + decode stash + dst histogram
    for (int n = gtid; n < N_NODES; n += gsz)
        g_pos4[n] = make_float4(pos[n * 3 + 0], pos[n * 3 + 1], pos[n * 3 + 2], 0.f);
    for (int e = gtid; e < N_EDGES; e += gsz) {
        int src, dst;
        if (i64) {
            const long long* p = (const long long*)ei;
            src = (int)p[e]; dst = (int)p[N_EDGES + e];
        } else {
            const int* p = (const int*)ei;
            src = p[e]; dst = p[N_EDGES + e];
        }
        g_tmp[e] = make_int2(src, dst);
        atomicAdd(&g_zero[dst], 1);
    }
    gbar(nb);

    // phase 2: block-local scan over chunk of CH nodes (2 sequential items per thread)
    int CH = (((N_NODES + nb - 1) / nb) + 1) & ~1;
    int base = b * CH;
    int idx0 = base + 2 * t;
    int idx1 = idx0 + 1;
    int lim = min(base + CH, N_NODES);
    int v0 = (idx0 < lim) ? g_zero[idx0] : 0;
    int v1 = (idx1 < lim) ? g_zero[idx1] : 0;
    int pairsum = v0 + v1;
    s_scan[t] = pairsum;
    __syncthreads();
#pragma unroll
    for (int off = 1; off < CSR_T; off <<= 1) {
        int tt = (t >= off) ? s_scan[t - off] : 0;
        __syncthreads();
        s_scan[t] += tt;
        __syncthreads();
    }
    int texcl = s_scan[t] - pairsum;
    if (t == CSR_T - 1) g_part[b] = s_scan[CSR_T - 1];
    gbar(nb);

    // phase 3: block 0 scans block partials (exclusive)
    if (b == 0) {
        int pv = (t < nb) ? g_part[t] : 0;
        s_scan[t] = pv;
        __syncthreads();
#pragma unroll
        for (int off = 1; off < CSR_T; off <<= 1) {
            int tt = (t >= off) ? s_scan[t - off] : 0;
            __syncthreads();
            s_scan[t] += tt;
            __syncthreads();
        }
        if (t < nb) g_part[t] = s_scan[t] - pv;
    }
    gbar(nb);

    // phase 4: write offsets + cursors
    {
        int pbase = g_part[b];
        if (idx0 < lim) { int o = pbase + texcl;      g_off[idx0] = o; g_cur[idx0] = o; }
        if (idx1 < lim) { int o = pbase + texcl + v0; g_off[idx1] = o; g_cur[idx1] = o; }
    }
    gbar(nb);

    // phase 5: scatter edges into CSR order (by dst); pack (src*8, dist half2)
    for (int e = gtid; e < N_EDGES; e += gsz) {
        int2 sd = g_tmp[e];
        float4 pd = __ldg(&g_pos4[sd.y]);
        float4 ps = __ldg(&g_pos4[sd.x]);
        float dx = pd.x - ps.x, dy = pd.y - ps.y, dz = pd.z - ps.z;
        float dist = sqrtf(dx * dx + dy * dy + dz * dz);
        __half2 dh = __float2half2_rn(dist);
        unsigned du = *reinterpret_cast<unsigned*>(&dh);
        int p = atomicAdd(&g_cur[sd.y], 1);
        g_epack[p] = make_int2(sd.x * 8, (int)du);
    }
}

// ---------------- precompute folded matrices ----------------
__global__ void __launch_bounds__(256) precompute_kernel(
    const float* __restrict__ enc_w2, const float* __restrict__ enc_b2,
    const float* __restrict__ msg_w1, const float* __restrict__ msg_b1,
    const float* __restrict__ msg_w2, const float* __restrict__ msg_b2,
    const float* __restrict__ upd_w1, const float* __restrict__ upd_b1,
    const float* __restrict__ upd_w2, const float* __restrict__ upd_b2,
    const float* __restrict__ out_w, const float* __restrict__ out_b) {
    int b = blockIdx.x;
    int t = threadIdx.x;
    if (b < 13) {
        int l = (b < 12) ? (b % 3) : 2;
        int kind = (b < 12) ? (b / 3) : 4;
        const float* Wp = (l == 0) ? enc_w2 : upd_w2 + (size_t)(l - 1) * 1024;
        const float* L; const float* R; float* P;
        switch (kind) {
            case 0: L = Wp;                      R = msg_w1 + (size_t)l * 2080;        P = c_Pa[l]; break;
            case 1: L = Wp;                      R = msg_w1 + (size_t)l * 2080 + 1024; P = c_Pb[l]; break;
            case 2: L = Wp;                      R = upd_w1 + (size_t)l * 2048;        P = c_P1[l]; break;
            case 3: L = msg_w2 + (size_t)l*1024; R = upd_w1 + (size_t)l * 2048 + 1024; P = c_P2[l]; break;
            default: L = upd_w2 + 2048;          R = out_w;                            P = c_Po;    break;
        }
        for (int e = t; e < 1024; e += 256) {
            int i = e >> 5, j = e & 31;
            float s = 0.f;
            for (int k = 0; k < 32; k++) s = fmaf(L[i * 32 + k], R[k * 32 + j], s);
            P[e] = s;
        }
    } else {
        for (int e = t; e < 416; e += 256) {
            int vid = e >> 5, j = e & 31;
            int l = vid % 3;
            const float* cp = (l == 0) ? enc_b2 : upd_b2 + (size_t)(l - 1) * 32;
            float s = 0.f;
            if (vid < 3) {
                const float* R = msg_w1 + (size_t)l * 2080;
                for (int k = 0; k < 32; k++) s = fmaf(cp[k], R[k * 32 + j], s);
                c_qa[l][j] = s;
            } else if (vid < 6) {
                const float* R = msg_w1 + (size_t)l * 2080 + 1024;
                for (int k = 0; k < 32; k++) s = fmaf(cp[k], R[k * 32 + j], s);
                c_qb[l][j] = s;
            } else if (vid < 9) {
                const float* R = upd_w1 + (size_t)l * 2048;
                for (int k = 0; k < 32; k++) s = fmaf(cp[k], R[k * 32 + j], s);
                c_q1[l][j] = s + upd_b1[l * 32 + j];
            } else if (vid < 12) {
                const float* R = upd_w1 + (size_t)l * 2048 + 1024;
                const float* mb = msg_b2 + (size_t)l * 32;
                for (int k = 0; k < 32; k++) s = fmaf(mb[k], R[k * 32 + j], s);
                c_v[l][j] = s;
            } else {
                const float* ub = upd_b2 + 2 * 32;
                for (int k = 0; k < 32; k++) s = fmaf(ub[k], out_w[k * 32 + j], s);
                c_qo[j] = s + out_b[j];
            }
        }
    }
}

// ---------------- encoder: h = relu(feat@w1+b1); A=h@Pa0+qa0; B=h@Pb0+qb0 ----------------
__global__ void __launch_bounds__(128) encoder_kernel(
    const float* __restrict__ feat,
    const float* __restrict__ w1, const float* __restrict__ b1) {
    __shared__ float  s_feat[128 * 33];
    __shared__ float4 s_w1[64 * 8];
    __shared__ float4 s_pa[256], s_pb[256];
    __shared__ float4 s_b1[8], s_qa[8], s_qb[8];
    for (int i = threadIdx.x; i < 512; i += 128) s_w1[i] = ((const float4*)w1)[i];
    for (int i = threadIdx.x; i < 256; i += 128) {
        s_pa[i] = ((const float4*)c_Pa[0])[i];
        s_pb[i] = ((const float4*)c_Pb[0])[i];
    }
    if (threadIdx.x < 8) {
        s_b1[threadIdx.x] = ((const float4*)b1)[threadIdx.x];
        s_qa[threadIdx.x] = ((const float4*)c_qa[0])[threadIdx.x];
        s_qb[threadIdx.x] = ((const float4*)c_qb[0])[threadIdx.x];
    }
    __syncthreads();
    int base = blockIdx.x * 128;
    int n = base + threadIdx.x;
    bool act = (n < N_NODES);

    ulonglong2 hacc[8];
#pragma unroll
    for (int i = 0; i < 8; i++) hacc[i] = pack4(s_b1[i]);

#pragma unroll
    for (int half = 0; half < 2; half++) {
        for (int j = threadIdx.x; j < 128 * 32; j += 128) {
            int r = j >> 5, col = j & 31;
            int nn = base + r;
            s_feat[r * 33 + col] =
                (nn < N_NODES) ? feat[(size_t)nn * 64 + half * 32 + col] : 0.f;
        }
        __syncthreads();
        const float* frow = &s_feat[threadIdx.x * 33];
#pragma unroll 8
        for (int k = 0; k < 32; k++) {
            float f = frow[k];
            unsigned long long f2;
            asm("mov.b64 %0, {%1, %1};" : "=l"(f2) : "f"(f));
            const ulonglong2* w = (const ulonglong2*)(s_w1 + (half * 32 + k) * 8);
#pragma unroll
            for (int i = 0; i < 8; i++) {
                ulonglong2 wv = w[i];
                asm("fma.rn.f32x2 %0, %1, %2, %0;" : "+l"(hacc[i].x) : "l"(f2), "l"(wv.x));
                asm("fma.rn.f32x2 %0, %1, %2, %0;" : "+l"(hacc[i].y) : "l"(f2), "l"(wv.y));
            }
        }
        __syncthreads();
    }
    float4 h[8];
#pragma unroll
    for (int i = 0; i < 8; i++) h[i] = relu4(unpack4(hacc[i]));

    ulonglong2 a[8], b[8];
#pragma unroll
    for (int i = 0; i < 8; i++) { a[i] = pack4(s_qa[i]); b[i] = pack4(s_qb[i]); }
    gemv32(s_pa, h, a);
    gemv32(s_pb, h, b);

    if (act) {
        ulonglong2* ph = (ulonglong2*)&g_h[(size_t)n * 8];
        ulonglong2* pa = (ulonglong2*)&g_A[(size_t)n * 8];
#pragma unroll
        for (int i = 0; i < 8; i++) {
            ph[i] = pack4(h[i]);
            pa[i] = a[i];
            g_Bh[(size_t)n * 8 + i] = f4_to_h4(unpack4(b[i]));
        }
    }
}

// ---------------- per layer: agg[n] = sum_e relu(A[n] + B[src_e] + d_e*c + b1) ----------------
// 8 lanes per node (comp c = lane&7), 4 nodes per warp. Half2 inner arithmetic,
// fp32 accumulation. epack carries (src*8, dist half2) — no per-edge cvt/IMAD.
__global__ void __launch_bounds__(256) agg_kernel(
    const float* __restrict__ w1c, const float* __restrict__ b1) {
    int warp = (blockIdx.x * 256 + threadIdx.x) >> 5;
    int lane = threadIdx.x & 31;
    int c = lane & 7;
    int n = warp * 4 + (lane >> 3);
    bool act = (n < N_NODES);

    float4 cvf = __ldg(((const float4*)w1c) + c);
    float4 bbf = __ldg(((const float4*)b1) + c);
    __half2 cv0 = __floats2half2_rn(cvf.x, cvf.y);
    __half2 cv1 = __floats2half2_rn(cvf.z, cvf.w);
    const __half2 z2 = __floats2half2_rn(0.f, 0.f);

    int start = 0, deg = 0;
    __half2 ab0 = z2, ab1 = z2;
    if (act) {
        start = __ldg(&g_off[n]);
        deg   = __ldg(&g_zero[n]);   // hist
        float4 abf = add4(g_A[(size_t)n * 8 + c], bbf);
        ab0 = __floats2half2_rn(abf.x, abf.y);
        ab1 = __floats2half2_rn(abf.z, abf.w);
    }
    const unsigned long long* Bc = g_Bh + c;

    float4 acc0 = make_float4(0.f, 0.f, 0.f, 0.f);
    float4 acc1 = make_float4(0.f, 0.f, 0.f, 0.f);
    int i = 0;
    for (; i + 1 < deg; i += 2) {
        int2 sd0 = __ldg(&g_epack[start + i]);
        int2 sd1 = __ldg(&g_epack[start + i + 1]);
        uint2 bh0 = __ldg((const uint2*)(Bc + sd0.x));
        uint2 bh1 = __ldg((const uint2*)(Bc + sd1.x));
        __half2 d0 = *reinterpret_cast<__half2*>(&sd0.y);
        __half2 d1 = *reinterpret_cast<__half2*>(&sd1.y);
        __half2 h00 = __hmax2(__hadd2(__hfma2(d0, cv0, *reinterpret_cast<__half2*>(&bh0.x)), ab0), z2);
        __half2 h01 = __hmax2(__hadd2(__hfma2(d0, cv1, *reinterpret_cast<__half2*>(&bh0.y)), ab1), z2);
        __half2 h10 = __hmax2(__hadd2(__hfma2(d1, cv0, *reinterpret_cast<__half2*>(&bh1.x)), ab0), z2);
        __half2 h11 = __hmax2(__hadd2(__hfma2(d1, cv1, *reinterpret_cast<__half2*>(&bh1.y)), ab1), z2);
        float2 f00 = __half22float2(h00), f01 = __half22float2(h01);
        float2 f10 = __half22float2(h10), f11 = __half22float2(h11);
        acc0.x += f00.x; acc0.y += f00.y; acc0.z += f01.x; acc0.w += f01.y;
        acc1.x += f10.x; acc1.y += f10.y; acc1.z += f11.x; acc1.w += f11.y;
    }
    if (i < deg) {
        int2 sd = __ldg(&g_epack[start + i]);
        uint2 bh = __ldg((const uint2*)(Bc + sd.x));
        __half2 d2 = *reinterpret_cast<__half2*>(&sd.y);
        __half2 h0 = __hmax2(__hadd2(__hfma2(d2, cv0, *reinterpret_cast<__half2*>(&bh.x)), ab0), z2);
        __half2 h1 = __hmax2(__hadd2(__hfma2(d2, cv1, *reinterpret_cast<__half2*>(&bh.y)), ab1), z2);
        float2 f0 = __half22float2(h0), f1 = __half22float2(h1);
        acc0.x += f0.x; acc0.y += f0.y; acc0.z += f1.x; acc0.w += f1.y;
    }
    if (act) g_agg[(size_t)n * 8 + c] = add4(acc0, acc1);
}

// ---------------- per layer update (folded) ----------------
__global__ void __launch_bounds__(128) update_kernel(int l, int last, float* __restrict__ outp) {
    __shared__ float4 s_p1[256], s_p2[256], s_pc[256], s_pd[256];
    __shared__ float4 s_q1[8], s_v[8], s_qc[8], s_qd[8];
    {
        const float* P1 = c_P1[l];
        const float* P2 = c_P2[l];
        const float* Pc = last ? c_Po : c_Pa[l + 1 < 3 ? l + 1 : 0];
        const float* Pd = last ? c_Po : c_Pb[l + 1 < 3 ? l + 1 : 0];
        for (int i = threadIdx.x; i < 256; i += 128) {
            s_p1[i] = ((const float4*)P1)[i];
            s_p2[i] = ((const float4*)P2)[i];
            s_pc[i] = ((const float4*)Pc)[i];
            s_pd[i] = ((const float4*)Pd)[i];
        }
        if (threadIdx.x < 8) {
            s_q1[threadIdx.x] = ((const float4*)c_q1[l])[threadIdx.x];
            s_v[threadIdx.x]  = ((const float4*)c_v[l])[threadIdx.x];
            const float* qc = last ? c_qo : c_qa[l + 1 < 3 ? l + 1 : 0];
            const float* qd = last ? c_qo : c_qb[l + 1 < 3 ? l + 1 : 0];
            s_qc[threadIdx.x] = ((const float4*)qc)[threadIdx.x];
            s_qd[threadIdx.x] = ((const float4*)qd)[threadIdx.x];
        }
    }
    __syncthreads();
    int n = blockIdx.x * blockDim.x + threadIdx.x;
    if (n >= N_NODES) return;

    float deg = (float)g_zero[n];
    ulonglong2 uacc[8];
#pragma unroll
    for (int i = 0; i < 8; i++) {
        float4 q = s_q1[i], vv = s_v[i];
        uacc[i] = pack4(make_float4(fmaf(deg, vv.x, q.x), fmaf(deg, vv.y, q.y),
                                    fmaf(deg, vv.z, q.z), fmaf(deg, vv.w, q.w)));
    }
    float4 hr[8];
#pragma unroll
    for (int i = 0; i < 8; i++) hr[i] = g_h[(size_t)n * 8 + i];
    gemv32(s_p1, hr, uacc);
    float4 ar[8];
#pragma unroll
    for (int i = 0; i < 8; i++) ar[i] = g_agg[(size_t)n * 8 + i];
    gemv32(s_p2, ar, uacc);

    float4 u[8];
#pragma unroll
    for (int i = 0; i < 8; i++) u[i] = relu4(unpack4(uacc[i]));

    ulonglong2 cacc[8];
#pragma unroll
    for (int i = 0; i < 8; i++) cacc[i] = pack4(s_qc[i]);
    gemv32(s_pc, u, cacc);

    if (!last) {
        ulonglong2 dacc[8];
#pragma unroll
        for (int i = 0; i < 8; i++) dacc[i] = pack4(s_qd[i]);
        gemv32(s_pd, u, dacc);
        ulonglong2* ph = (ulonglong2*)&g_h[(size_t)n * 8];
        ulonglong2* pa = (ulonglong2*)&g_A[(size_t)n * 8];
#pragma unroll
        for (int i = 0; i < 8; i++) {
            ph[i] = pack4(u[i]);
            pa[i] = cacc[i];
            g_Bh[(size_t)n * 8 + i] = f4_to_h4(unpack4(dacc[i]));
        }
    } else {
        ulonglong2* orow = (ulonglong2*)(outp + (size_t)n * 32);
#pragma unroll
        for (int i = 0; i < 8; i++) orow[i] = cacc[i];
    }
}

// ---------------- launch ----------------
extern "C" void kernel_launch(void* const* d_in, const int* in_sizes, int n_in,
                              void* d_out, int out_size) {
    const float* node_feat = (const float*)d_in[0];
    const float* pos       = (const float*)d_in[1];
    const void*  ei        = d_in[2];
    const float* enc_w1    = (const float*)d_in[3];
    const float* enc_b1    = (const float*)d_in[4];
    const float* enc_w2    = (const float*)d_in[5];
    const float* enc_b2    = (const float*)d_in[6];
    const float* msg_w1    = (const float*)d_in[7];
    const float* msg_b1    = (const float*)d_in[8];
    const float* msg_w2    = (const float*)d_in[9];
    const float* msg_b2    = (const float*)d_in[10];
    const float* upd_w1    = (const float*)d_in[11];
    const float* upd_b1    = (const float*)d_in[12];
    const float* upd_w2    = (const float*)d_in[13];
    const float* upd_b2    = (const float*)d_in[14];
    const float* out_w     = (const float*)d_in[15];
    const float* out_b     = (const float*)d_in[16];
    float* out = (float*)d_out;

    const int NODE_BLOCKS = (N_NODES + 127) / 128;
    const int AGG_BLOCKS  = (((N_NODES + 3) / 4) * 32 + 255) / 256;

    // persistent CSR grid: <= 1 block/SM (co-residency guaranteed; leaves SMs for s1 chain)
    int nsm = 0, occ = 0;
    cudaDeviceGetAttribute(&nsm, cudaDevAttrMultiProcessorCount, 0);
    cudaOccupancyMaxActiveBlocksPerMultiprocessor(&occ, csr_kernel, CSR_T, 0);
    if (occ < 1) occ = 1;
    int csr_blocks = occ * nsm;
    if (csr_blocks > nsm) csr_blocks = nsm;   // cap at 1 block/SM
    if (csr_blocks > 512) csr_blocks = 512;

    cudaStream_t s1;
    cudaStreamCreateWithFlags(&s1, cudaStreamNonBlocking);
    cudaEvent_t ev_fork, ev_join;
    cudaEventCreateWithFlags(&ev_fork, cudaEventDisableTiming);
    cudaEventCreateWithFlags(&ev_join, cudaEventDisableTiming);

    cudaEventRecord(ev_fork, 0);
    cudaStreamWaitEvent(s1, ev_fork, 0);

    // chain A (capture stream): memset -> persistent CSR build
    void* p_zero = nullptr;
    cudaGetSymbolAddress(&p_zero, g_zero);
    cudaMemsetAsync(p_zero, 0, (N_NODES + 2) * sizeof(int), 0);
    csr_kernel<<<csr_blocks, CSR_T>>>(ei, pos);                        // kernel #1

    // chain B (stream s1): precompute -> encoder
    precompute_kernel<<<14, 256, 0, s1>>>(enc_w2, enc_b2, msg_w1, msg_b1, msg_w2, msg_b2,
                                          upd_w1, upd_b1, upd_w2, upd_b2, out_w, out_b); // #2
    encoder_kernel<<<NODE_BLOCKS, 128, 0, s1>>>(node_feat, enc_w1, enc_b1);              // #3
    cudaEventRecord(ev_join, s1);

    cudaStreamWaitEvent(0, ev_join, 0);

    for (int l = 0; l < 3; l++) {
        const float* w1 = msg_w1 + (size_t)l * 65 * 32;
        agg_kernel<<<AGG_BLOCKS, 256>>>(w1 + 64 * 32, msg_b1 + (size_t)l * 32);  // l=0 -> #4 (profiled)
        update_kernel<<<NODE_BLOCKS, 128>>>(l, l == 2, out);
    }
}

// round 13
// speedup vs baseline: 1.0136x; 1.0115x over previous
#include <cuda_runtime.h>
#include <cuda_fp16.h>
#include <math.h>

#define N_NODES 100000
#define N_EDGES 1600000
#define HID 32
#define CSR_T 512

// ---------------- device scratch ----------------
__device__ float4 g_h  [N_NODES * 8];
__device__ float4 g_A  [N_NODES * 8];
__device__ unsigned long long g_Bh[N_NODES * 8];   // fp16 B table
__device__ float4 g_agg[N_NODES * 8];
__device__ float4 g_pos4[N_NODES];
__device__ int2   g_epack[N_EDGES];               // CSR by dst: (src*8, dist f32 bits)
__device__ int2   g_tmp  [N_EDGES];               // decoded (src, dst)
// zero region: [0, N_NODES) = hist; [N_NODES] = barrier count; [N_NODES+1] = barrier gen
__device__ __align__(8) int g_zero[N_NODES + 2];
__device__ int    g_off [N_NODES];
__device__ int    g_cur [N_NODES];
__device__ int    g_part[512];

// folded matrices/vectors
__device__ float  c_Pa[3][1024], c_Pb[3][1024], c_P1[3][1024], c_P2[3][1024], c_Po[1024];
__device__ float  c_qa[3][32],  c_qb[3][32],  c_q1[3][32],  c_v[3][32],  c_qo[32];

// ---------------- helpers ----------------
__device__ __forceinline__ float4 fma4(float f, float4 w, float4 a) {
    a.x = fmaf(f, w.x, a.x); a.y = fmaf(f, w.y, a.y);
    a.z = fmaf(f, w.z, a.z); a.w = fmaf(f, w.w, a.w);
    return a;
}
__device__ __forceinline__ float4 add4(float4 a, float4 b) {
    a.x += b.x; a.y += b.y; a.z += b.z; a.w += b.w; return a;
}
__device__ __forceinline__ float4 relu4(float4 v) {
    v.x = fmaxf(v.x, 0.f); v.y = fmaxf(v.y, 0.f);
    v.z = fmaxf(v.z, 0.f); v.w = fmaxf(v.w, 0.f); return v;
}
#define COMP(v, c) ((c) == 0 ? (v).x : (c) == 1 ? (v).y : (c) == 2 ? (v).z : (v).w)

__device__ __forceinline__ ulonglong2 pack4(float4 v) {
    ulonglong2 r;
    asm("mov.b64 %0, {%1, %2};" : "=l"(r.x) : "f"(v.x), "f"(v.y));
    asm("mov.b64 %0, {%1, %2};" : "=l"(r.y) : "f"(v.z), "f"(v.w));
    return r;
}
__device__ __forceinline__ float4 unpack4(ulonglong2 v) {
    float4 r;
    asm("mov.b64 {%0, %1}, %2;" : "=f"(r.x), "=f"(r.y) : "l"(v.x));
    asm("mov.b64 {%0, %1}, %2;" : "=f"(r.z), "=f"(r.w) : "l"(v.y));
    return r;
}
__device__ __forceinline__ unsigned long long f4_to_h4(float4 v) {
    __half2 h0 = __floats2half2_rn(v.x, v.y);
    __half2 h1 = __floats2half2_rn(v.z, v.w);
    unsigned lo = *reinterpret_cast<unsigned*>(&h0);
    unsigned hi = *reinterpret_cast<unsigned*>(&h1);
    return (unsigned long long)lo | ((unsigned long long)hi << 32);
}
__device__ __forceinline__ float4 h4_to_f4(unsigned long long v) {
    unsigned lo = (unsigned)v, hi = (unsigned)(v >> 32);
    __half2 h0 = *reinterpret_cast<__half2*>(&lo);
    __half2 h1 = *reinterpret_cast<__half2*>(&hi);
    float2 f0 = __half22float2(h0), f1 = __half22float2(h1);
    return make_float4(f0.x, f0.y, f1.x, f1.y);
}

// full gemv: acc[8] += x @ W
__device__ __forceinline__ void gemv32(const float4* __restrict__ sW,
                                       const float4* xr, ulonglong2* acc) {
#pragma unroll
    for (int k = 0; k < 32; k++) {
        float f = COMP(xr[k >> 2], k & 3);
        unsigned long long f2;
        asm("mov.b64 %0, {%1, %1};" : "=l"(f2) : "f"(f));
        const ulonglong2* w = (const ulonglong2*)(sW + k * 8);
#pragma unroll
        for (int i = 0; i < 8; i++) {
            ulonglong2 wv = w[i];
            asm("fma.rn.f32x2 %0, %1, %2, %0;" : "+l"(acc[i].x) : "l"(f2), "l"(wv.x));
            asm("fma.rn.f32x2 %0, %1, %2, %0;" : "+l"(acc[i].y) : "l"(f2), "l"(wv.y));
        }
    }
}

// half gemv: acc[4] += x @ W[:, 16h:16h+16]   (column half h of the 32-wide output)
__device__ __forceinline__ void gemv32h(const float4* __restrict__ sW,
                                        const float4* xr, ulonglong2* acc, int h) {
#pragma unroll
    for (int k = 0; k < 32; k++) {
        float f = COMP(xr[k >> 2], k & 3);
        unsigned long long f2;
        asm("mov.b64 %0, {%1, %1};" : "=l"(f2) : "f"(f));
        const ulonglong2* w = (const ulonglong2*)(sW + k * 8 + h * 4);
#pragma unroll
        for (int i = 0; i < 4; i++) {
            ulonglong2 wv = w[i];
            asm("fma.rn.f32x2 %0, %1, %2, %0;" : "+l"(acc[i].x) : "l"(f2), "l"(wv.x));
            asm("fma.rn.f32x2 %0, %1, %2, %0;" : "+l"(acc[i].y) : "l"(f2), "l"(wv.y));
        }
    }
}

// ---------------- software grid barrier ----------------
__device__ __forceinline__ void gbar(int nb) {
    __syncthreads();
    if (threadIdx.x == 0) {
        int* cnt = &g_zero[N_NODES];
        int* gen = &g_zero[N_NODES + 1];
        int g = atomicAdd(gen, 0);
        __threadfence();
        if (atomicAdd(cnt, 1) == nb - 1) {
            *cnt = 0;
            __threadfence();
            atomicExch(gen, g + 1);
        } else {
            while (atomicAdd(gen, 0) == g) { __nanosleep(64); }
        }
        __threadfence();
    }
    __syncthreads();
}

// ---------------- persistent CSR build ----------------
__global__ void __launch_bounds__(CSR_T) csr_kernel(const void* ei, const float* __restrict__ pos) {
    __shared__ int s_i64;
    __shared__ int s_scan[CSR_T];
    int t = threadIdx.x;
    int b = blockIdx.x;
    int nb = gridDim.x;
    int gtid = b * CSR_T + t;
    int gsz = nb * CSR_T;

    if (t < 32) {
        int v = ((const int*)ei)[2 * t + 1];
        unsigned m = __ballot_sync(0xffffffffu, v != 0);
        if (t == 0) s_i64 = (m == 0);
    }
    __syncthreads();
    int i64 = s_i64;

    for (int n = gtid; n < N_NODES; n += gsz)
        g_pos4[n] = make_float4(pos[n * 3 + 0], pos[n * 3 + 1], pos[n * 3 + 2], 0.f);
    for (int e = gtid; e < N_EDGES; e += gsz) {
        int src, dst;
        if (i64) {
            const long long* p = (const long long*)ei;
            src = (int)p[e]; dst = (int)p[N_EDGES + e];
        } else {
            const int* p = (const int*)ei;
            src = p[e]; dst = p[N_EDGES + e];
        }
        g_tmp[e] = make_int2(src, dst);
        atomicAdd(&g_zero[dst], 1);
    }
    gbar(nb);

    int CH = (((N_NODES + nb - 1) / nb) + 1) & ~1;
    int base = b * CH;
    int idx0 = base + 2 * t;
    int idx1 = idx0 + 1;
    int lim = min(base + CH, N_NODES);
    int v0 = (idx0 < lim) ? g_zero[idx0] : 0;
    int v1 = (idx1 < lim) ? g_zero[idx1] : 0;
    int pairsum = v0 + v1;
    s_scan[t] = pairsum;
    __syncthreads();
#pragma unroll
    for (int off = 1; off < CSR_T; off <<= 1) {
        int tt = (t >= off) ? s_scan[t - off] : 0;
        __syncthreads();
        s_scan[t] += tt;
        __syncthreads();
    }
    int texcl = s_scan[t] - pairsum;
    if (t == CSR_T - 1) g_part[b] = s_scan[CSR_T - 1];
    gbar(nb);

    if (b == 0) {
        int pv = (t < nb) ? g_part[t] : 0;
        s_scan[t] = pv;
        __syncthreads();
#pragma unroll
        for (int off = 1; off < CSR_T; off <<= 1) {
            int tt = (t >= off) ? s_scan[t - off] : 0;
            __syncthreads();
            s_scan[t] += tt;
            __syncthreads();
        }
        if (t < nb) g_part[t] = s_scan[t] - pv;
    }
    gbar(nb);

    {
        int pbase = g_part[b];
        if (idx0 < lim) { int o = pbase + texcl;      g_off[idx0] = o; g_cur[idx0] = o; }
        if (idx1 < lim) { int o = pbase + texcl + v0; g_off[idx1] = o; g_cur[idx1] = o; }
    }
    gbar(nb);

    for (int e = gtid; e < N_EDGES; e += gsz) {
        int2 sd = g_tmp[e];
        float4 pd = __ldg(&g_pos4[sd.y]);
        float4 ps = __ldg(&g_pos4[sd.x]);
        float dx = pd.x - ps.x, dy = pd.y - ps.y, dz = pd.z - ps.z;
        float dist = sqrtf(dx * dx + dy * dy + dz * dz);
        int p = atomicAdd(&g_cur[sd.y], 1);
        g_epack[p] = make_int2(sd.x * 8, __float_as_int(dist));
    }
}

// ---------------- precompute folded matrices ----------------
__global__ void __launch_bounds__(256) precompute_kernel(
    const float* __restrict__ enc_w2, const float* __restrict__ enc_b2,
    const float* __restrict__ msg_w1, const float* __restrict__ msg_b1,
    const float* __restrict__ msg_w2, const float* __restrict__ msg_b2,
    const float* __restrict__ upd_w1, const float* __restrict__ upd_b1,
    const float* __restrict__ upd_w2, const float* __restrict__ upd_b2,
    const float* __restrict__ out_w, const float* __restrict__ out_b) {
    int b = blockIdx.x;
    int t = threadIdx.x;
    if (b < 13) {
        int l = (b < 12) ? (b % 3) : 2;
        int kind = (b < 12) ? (b / 3) : 4;
        const float* Wp = (l == 0) ? enc_w2 : upd_w2 + (size_t)(l - 1) * 1024;
        const float* L; const float* R; float* P;
        switch (kind) {
            case 0: L = Wp;                      R = msg_w1 + (size_t)l * 2080;        P = c_Pa[l]; break;
            case 1: L = Wp;                      R = msg_w1 + (size_t)l * 2080 + 1024; P = c_Pb[l]; break;
            case 2: L = Wp;                      R = upd_w1 + (size_t)l * 2048;        P = c_P1[l]; break;
            case 3: L = msg_w2 + (size_t)l*1024; R = upd_w1 + (size_t)l * 2048 + 1024; P = c_P2[l]; break;
            default: L = upd_w2 + 2048;          R = out_w;                            P = c_Po;    break;
        }
        for (int e = t; e < 1024; e += 256) {
            int i = e >> 5, j = e & 31;
            float s = 0.f;
            for (int k = 0; k < 32; k++) s = fmaf(L[i * 32 + k], R[k * 32 + j], s);
            P[e] = s;
        }
    } else {
        for (int e = t; e < 416; e += 256) {
            int vid = e >> 5, j = e & 31;
            int l = vid % 3;
            const float* cp = (l == 0) ? enc_b2 : upd_b2 + (size_t)(l - 1) * 32;
            float s = 0.f;
            if (vid < 3) {
                const float* R = msg_w1 + (size_t)l * 2080;
                for (int k = 0; k < 32; k++) s = fmaf(cp[k], R[k * 32 + j], s);
                c_qa[l][j] = s;
            } else if (vid < 6) {
                const float* R = msg_w1 + (size_t)l * 2080 + 1024;
                for (int k = 0; k < 32; k++) s = fmaf(cp[k], R[k * 32 + j], s);
                c_qb[l][j] = s;
            } else if (vid < 9) {
                const float* R = upd_w1 + (size_t)l * 2048;
                for (int k = 0; k < 32; k++) s = fmaf(cp[k], R[k * 32 + j], s);
                c_q1[l][j] = s + upd_b1[l * 32 + j];
            } else if (vid < 12) {
                const float* R = upd_w1 + (size_t)l * 2048 + 1024;
                const float* mb = msg_b2 + (size_t)l * 32;
                for (int k = 0; k < 32; k++) s = fmaf(mb[k], R[k * 32 + j], s);
                c_v[l][j] = s;
            } else {
                const float* ub = upd_b2 + 2 * 32;
                for (int k = 0; k < 32; k++) s = fmaf(ub[k], out_w[k * 32 + j], s);
                c_qo[j] = s + out_b[j];
            }
        }
    }
}

// ---------------- encoder ----------------
__global__ void __launch_bounds__(128) encoder_kernel(
    const float* __restrict__ feat,
    const float* __restrict__ w1, const float* __restrict__ b1) {
    __shared__ float  s_feat[128 * 33];
    __shared__ float4 s_w1[64 * 8];
    __shared__ float4 s_pa[256], s_pb[256];
    __shared__ float4 s_b1[8], s_qa[8], s_qb[8];
    for (int i = threadIdx.x; i < 512; i += 128) s_w1[i] = ((const float4*)w1)[i];
    for (int i = threadIdx.x; i < 256; i += 128) {
        s_pa[i] = ((const float4*)c_Pa[0])[i];
        s_pb[i] = ((const float4*)c_Pb[0])[i];
    }
    if (threadIdx.x < 8) {
        s_b1[threadIdx.x] = ((const float4*)b1)[threadIdx.x];
        s_qa[threadIdx.x] = ((const float4*)c_qa[0])[threadIdx.x];
        s_qb[threadIdx.x] = ((const float4*)c_qb[0])[threadIdx.x];
    }
    __syncthreads();
    int base = blockIdx.x * 128;
    int n = base + threadIdx.x;
    bool act = (n < N_NODES);

    ulonglong2 hacc[8];
#pragma unroll
    for (int i = 0; i < 8; i++) hacc[i] = pack4(s_b1[i]);

#pragma unroll
    for (int half = 0; half < 2; half++) {
        for (int j = threadIdx.x; j < 128 * 32; j += 128) {
            int r = j >> 5, col = j & 31;
            int nn = base + r;
            s_feat[r * 33 + col] =
                (nn < N_NODES) ? feat[(size_t)nn * 64 + half * 32 + col] : 0.f;
        }
        __syncthreads();
        const float* frow = &s_feat[threadIdx.x * 33];
#pragma unroll 8
        for (int k = 0; k < 32; k++) {
            float f = frow[k];
            unsigned long long f2;
            asm("mov.b64 %0, {%1, %1};" : "=l"(f2) : "f"(f));
            const ulonglong2* w = (const ulonglong2*)(s_w1 + (half * 32 + k) * 8);
#pragma unroll
            for (int i = 0; i < 8; i++) {
                ulonglong2 wv = w[i];
                asm("fma.rn.f32x2 %0, %1, %2, %0;" : "+l"(hacc[i].x) : "l"(f2), "l"(wv.x));
                asm("fma.rn.f32x2 %0, %1, %2, %0;" : "+l"(hacc[i].y) : "l"(f2), "l"(wv.y));
            }
        }
        __syncthreads();
    }
    float4 h[8];
#pragma unroll
    for (int i = 0; i < 8; i++) h[i] = relu4(unpack4(hacc[i]));

    ulonglong2 a[8], b[8];
#pragma unroll
    for (int i = 0; i < 8; i++) { a[i] = pack4(s_qa[i]); b[i] = pack4(s_qb[i]); }
    gemv32(s_pa, h, a);
    gemv32(s_pb, h, b);

    if (act) {
        ulonglong2* ph = (ulonglong2*)&g_h[(size_t)n * 8];
        ulonglong2* pa = (ulonglong2*)&g_A[(size_t)n * 8];
#pragma unroll
        for (int i = 0; i < 8; i++) {
            ph[i] = pack4(h[i]);
            pa[i] = a[i];
            g_Bh[(size_t)n * 8 + i] = f4_to_h4(unpack4(b[i]));
        }
    }
}

// ---------------- per layer agg: fp32 math, fp16 B storage, src*8 in epack ----------------
__global__ void __launch_bounds__(256) agg_kernel(
    const float* __restrict__ w1c, const float* __restrict__ b1) {
    int warp = (blockIdx.x * 256 + threadIdx.x) >> 5;
    int lane = threadIdx.x & 31;
    int c = lane & 7;
    int n = warp * 4 + (lane >> 3);
    bool act = (n < N_NODES);

    float4 cv = __ldg(((const float4*)w1c) + c);
    float4 bb = __ldg(((const float4*)b1) + c);

    int start = 0, deg = 0;
    if (act) {
        start = __ldg(&g_off[n]);
        deg   = __ldg(&g_zero[n]);   // hist
    }
    float4 ab = make_float4(0.f, 0.f, 0.f, 0.f);
    if (act) ab = add4(g_A[(size_t)n * 8 + c], bb);
    const unsigned long long* Bc = g_Bh + c;

    float4 acc0 = make_float4(0.f, 0.f, 0.f, 0.f);
    float4 acc1 = make_float4(0.f, 0.f, 0.f, 0.f);
    int i = 0;
    for (; i + 1 < deg; i += 2) {
        int2 sd0 = __ldg(&g_epack[start + i]);
        int2 sd1 = __ldg(&g_epack[start + i + 1]);
        float4 b0 = h4_to_f4(__ldg(Bc + sd0.x));
        float4 b1v = h4_to_f4(__ldg(Bc + sd1.x));
        acc0 = add4(acc0, relu4(fma4(__int_as_float(sd0.y), cv, add4(ab, b0))));
        acc1 = add4(acc1, relu4(fma4(__int_as_float(sd1.y), cv, add4(ab, b1v))));
    }
    if (i < deg) {
        int2 sd = __ldg(&g_epack[start + i]);
        float4 b = h4_to_f4(__ldg(Bc + sd.x));
        acc0 = add4(acc0, relu4(fma4(__int_as_float(sd.y), cv, add4(ab, b))));
    }
    if (act) g_agg[(size_t)n * 8 + c] = add4(acc0, acc1);
}

// ---------------- per layer update: 2 threads per node (column halves) ----------------
__global__ void __launch_bounds__(256) update_kernel(int l, int last, float* __restrict__ outp) {
    __shared__ float4 s_p1[256], s_p2[256], s_pc[256], s_pd[256];
    __shared__ float4 s_q1[8], s_v[8], s_qc[8], s_qd[8];
    {
        const float* P1 = c_P1[l];
        const float* P2 = c_P2[l];
        const float* Pc = last ? c_Po : c_Pa[l + 1 < 3 ? l + 1 : 0];
        const float* Pd = last ? c_Po : c_Pb[l + 1 < 3 ? l + 1 : 0];
        for (int i = threadIdx.x; i < 256; i += 256) { }  // (no-op; loads below stride 256)
        for (int i = threadIdx.x; i < 256; i += 256) { }
        for (int i = threadIdx.x; i < 256; i += 256) { }
        for (int i = threadIdx.x; i < 256; i += 256) { }
        for (int i = threadIdx.x; i < 256; i += 256) {
            s_p1[i] = ((const float4*)P1)[i];
            s_p2[i] = ((const float4*)P2)[i];
            s_pc[i] = ((const float4*)Pc)[i];
            s_pd[i] = ((const float4*)Pd)[i];
        }
        if (threadIdx.x < 8) {
            s_q1[threadIdx.x] = ((const float4*)c_q1[l])[threadIdx.x];
            s_v[threadIdx.x]  = ((const float4*)c_v[l])[threadIdx.x];
            const float* qc = last ? c_qo : c_qa[l + 1 < 3 ? l + 1 : 0];
            const float* qd = last ? c_qo : c_qb[l + 1 < 3 ? l + 1 : 0];
            s_qc[threadIdx.x] = ((const float4*)qc)[threadIdx.x];
            s_qd[threadIdx.x] = ((const float4*)qd)[threadIdx.x];
        }
    }
    __syncthreads();
    int gt = blockIdx.x * 256 + threadIdx.x;
    int n = gt >> 1;
    int h = gt & 1;
    if (n >= N_NODES) return;

    float deg = (float)g_zero[n];
    ulonglong2 uacc[4];
#pragma unroll
    for (int i = 0; i < 4; i++) {
        float4 q = s_q1[4 * h + i], vv = s_v[4 * h + i];
        uacc[i] = pack4(make_float4(fmaf(deg, vv.x, q.x), fmaf(deg, vv.y, q.y),
                                    fmaf(deg, vv.z, q.z), fmaf(deg, vv.w, q.w)));
    }
    float4 hr[8];
#pragma unroll
    for (int i = 0; i < 8; i++) hr[i] = g_h[(size_t)n * 8 + i];
    gemv32h(s_p1, hr, uacc, h);
    float4 ar[8];
#pragma unroll
    for (int i = 0; i < 8; i++) ar[i] = g_agg[(size_t)n * 8 + i];
    gemv32h(s_p2, ar, uacc, h);

    float4 uh[4];
#pragma unroll
    for (int i = 0; i < 4; i++) uh[i] = relu4(unpack4(uacc[i]));

    // assemble full u[8]: own half + partner's half via shfl.xor 1
    float4 u[8];
#pragma unroll
    for (int i = 0; i < 4; i++) {
        u[4 * h + i] = uh[i];
        float4 o;
        o.x = __shfl_xor_sync(0xffffffffu, uh[i].x, 1);
        o.y = __shfl_xor_sync(0xffffffffu, uh[i].y, 1);
        o.z = __shfl_xor_sync(0xffffffffu, uh[i].z, 1);
        o.w = __shfl_xor_sync(0xffffffffu, uh[i].w, 1);
        u[4 * (1 - h) + i] = o;
    }

    ulonglong2 cacc[4];
#pragma unroll
    for (int i = 0; i < 4; i++) cacc[i] = pack4(s_qc[4 * h + i]);
    gemv32h(s_pc, u, cacc, h);

    if (!last) {
        ulonglong2 dacc[4];
#pragma unroll
        for (int i = 0; i < 4; i++) dacc[i] = pack4(s_qd[4 * h + i]);
        gemv32h(s_pd, u, dacc, h);
        ulonglong2* ph = (ulonglong2*)&g_h[(size_t)n * 8];
        ulonglong2* pa = (ulonglong2*)&g_A[(size_t)n * 8];
#pragma unroll
        for (int i = 0; i < 4; i++) {
            ph[4 * h + i] = pack4(uh[i]);
            pa[4 * h + i] = cacc[i];
            g_Bh[(size_t)n * 8 + 4 * h + i] = f4_to_h4(unpack4(dacc[i]));
        }
    } else {
        ulonglong2* orow = (ulonglong2*)(outp + (size_t)n * 32);
#pragma unroll
        for (int i = 0; i < 4; i++) orow[4 * h + i] = cacc[i];
    }
}

// ---------------- launch ----------------
extern "C" void kernel_launch(void* const* d_in, const int* in_sizes, int n_in,
                              void* d_out, int out_size) {
    const float* node_feat = (const float*)d_in[0];
    const float* pos       = (const float*)d_in[1];
    const void*  ei        = d_in[2];
    const float* enc_w1    = (const float*)d_in[3];
    const float* enc_b1    = (const float*)d_in[4];
    const float* enc_w2    = (const float*)d_in[5];
    const float* enc_b2    = (const float*)d_in[6];
    const float* msg_w1    = (const float*)d_in[7];
    const float* msg_b1    = (const float*)d_in[8];
    const float* msg_w2    = (const float*)d_in[9];
    const float* msg_b2    = (const float*)d_in[10];
    const float* upd_w1    = (const float*)d_in[11];
    const float* upd_b1    = (const float*)d_in[12];
    const float* upd_w2    = (const float*)d_in[13];
    const float* upd_b2    = (const float*)d_in[14];
    const float* out_w     = (const float*)d_in[15];
    const float* out_b     = (const float*)d_in[16];
    float* out = (float*)d_out;

    const int NODE_BLOCKS = (N_NODES + 127) / 128;
    const int UPD_BLOCKS  = (2 * N_NODES + 255) / 256;
    const int AGG_BLOCKS  = (((N_NODES + 3) / 4) * 32 + 255) / 256;

    int nsm = 0, occ = 0;
    cudaDeviceGetAttribute(&nsm, cudaDevAttrMultiProcessorCount, 0);
    cudaOccupancyMaxActiveBlocksPerMultiprocessor(&occ, csr_kernel, CSR_T, 0);
    if (occ < 1) occ = 1;
    int csr_blocks = occ * nsm;
    if (csr_blocks > nsm) csr_blocks = nsm;
    if (csr_blocks > 512) csr_blocks = 512;

    cudaStream_t s1;
    cudaStreamCreateWithFlags(&s1, cudaStreamNonBlocking);
    cudaEvent_t ev_fork, ev_join;
    cudaEventCreateWithFlags(&ev_fork, cudaEventDisableTiming);
    cudaEventCreateWithFlags(&ev_join, cudaEventDisableTiming);

    cudaEventRecord(ev_fork, 0);
    cudaStreamWaitEvent(s1, ev_fork, 0);

    void* p_zero = nullptr;
    cudaGetSymbolAddress(&p_zero, g_zero);
    cudaMemsetAsync(p_zero, 0, (N_NODES + 2) * sizeof(int), 0);
    csr_kernel<<<csr_blocks, CSR_T>>>(ei, pos);                        // kernel #1

    precompute_kernel<<<14, 256, 0, s1>>>(enc_w2, enc_b2, msg_w1, msg_b1, msg_w2, msg_b2,
                                          upd_w1, upd_b1, upd_w2, upd_b2, out_w, out_b); // #2
    encoder_kernel<<<NODE_BLOCKS, 128, 0, s1>>>(node_feat, enc_w1, enc_b1);              // #3
    cudaEventRecord(ev_join, s1);

    cudaStreamWaitEvent(0, ev_join, 0);

    for (int l = 0; l < 3; l++) {
        const float* w1 = msg_w1 + (size_t)l * 65 * 32;
        agg_kernel<<<AGG_BLOCKS, 256>>>(w1 + 64 * 32, msg_b1 + (size_t)l * 32);  // l=0 -> #4 (profiled)
        update_kernel<<<UPD_BLOCKS, 256>>>(l, l == 2, out);
    }
}

// round 14
// speedup vs baseline: 1.0377x; 1.0237x over previous
#include <cuda_runtime.h>
#include <cuda_fp16.h>
#include <math.h>

#define N_NODES 100000
#define N_EDGES 1600000
#define HID 32
#define CSR_T 512

// ---------------- device scratch ----------------
__device__ float4 g_h  [N_NODES * 8];
__device__ float4 g_A  [N_NODES * 8];
__device__ unsigned long long g_Bh[N_NODES * 8];   // fp16 B table
__device__ float4 g_agg[N_NODES * 8];
__device__ float4 g_pos4[N_NODES];
__device__ __align__(16) int2 g_epack[N_EDGES];   // CSR by dst: (src*8, dist f32 bits)
__device__ int2   g_tmp  [N_EDGES];               // decoded (src, dst)
// region: [0, N_NODES) = hist (zeroed in csr phase 0); [N_NODES] = barrier cnt; [N_NODES+1] = gen
__device__ __align__(8) int g_zero[N_NODES + 2];
__device__ int    g_off [N_NODES];
__device__ int    g_cur [N_NODES];
__device__ int    g_part[512];

// folded matrices/vectors
__device__ float  c_Pa[3][1024], c_Pb[3][1024], c_P1[3][1024], c_P2[3][1024], c_Po[1024];
__device__ float  c_qa[3][32],  c_qb[3][32],  c_q1[3][32],  c_v[3][32],  c_qo[32];

// ---------------- helpers ----------------
__device__ __forceinline__ float4 fma4(float f, float4 w, float4 a) {
    a.x = fmaf(f, w.x, a.x); a.y = fmaf(f, w.y, a.y);
    a.z = fmaf(f, w.z, a.z); a.w = fmaf(f, w.w, a.w);
    return a;
}
__device__ __forceinline__ float4 add4(float4 a, float4 b) {
    a.x += b.x; a.y += b.y; a.z += b.z; a.w += b.w; return a;
}
__device__ __forceinline__ float4 relu4(float4 v) {
    v.x = fmaxf(v.x, 0.f); v.y = fmaxf(v.y, 0.f);
    v.z = fmaxf(v.z, 0.f); v.w = fmaxf(v.w, 0.f); return v;
}
#define COMP(v, c) ((c) == 0 ? (v).x : (c) == 1 ? (v).y : (c) == 2 ? (v).z : (v).w)

__device__ __forceinline__ ulonglong2 pack4(float4 v) {
    ulonglong2 r;
    asm("mov.b64 %0, {%1, %2};" : "=l"(r.x) : "f"(v.x), "f"(v.y));
    asm("mov.b64 %0, {%1, %2};" : "=l"(r.y) : "f"(v.z), "f"(v.w));
    return r;
}
__device__ __forceinline__ float4 unpack4(ulonglong2 v) {
    float4 r;
    asm("mov.b64 {%0, %1}, %2;" : "=f"(r.x), "=f"(r.y) : "l"(v.x));
    asm("mov.b64 {%0, %1}, %2;" : "=f"(r.z), "=f"(r.w) : "l"(v.y));
    return r;
}
__device__ __forceinline__ unsigned long long f4_to_h4(float4 v) {
    __half2 h0 = __floats2half2_rn(v.x, v.y);
    __half2 h1 = __floats2half2_rn(v.z, v.w);
    unsigned lo = *reinterpret_cast<unsigned*>(&h0);
    unsigned hi = *reinterpret_cast<unsigned*>(&h1);
    return (unsigned long long)lo | ((unsigned long long)hi << 32);
}
__device__ __forceinline__ float4 h4_to_f4(unsigned long long v) {
    unsigned lo = (unsigned)v, hi = (unsigned)(v >> 32);
    __half2 h0 = *reinterpret_cast<__half2*>(&lo);
    __half2 h1 = *reinterpret_cast<__half2*>(&hi);
    float2 f0 = __half22float2(h0), f1 = __half22float2(h1);
    return make_float4(f0.x, f0.y, f1.x, f1.y);
}

// full gemv: acc[8] += x @ W
__device__ __forceinline__ void gemv32(const float4* __restrict__ sW,
                                       const float4* xr, ulonglong2* acc) {
#pragma unroll
    for (int k = 0; k < 32; k++) {
        float f = COMP(xr[k >> 2], k & 3);
        unsigned long long f2;
        asm("mov.b64 %0, {%1, %1};" : "=l"(f2) : "f"(f));
        const ulonglong2* w = (const ulonglong2*)(sW + k * 8);
#pragma unroll
        for (int i = 0; i < 8; i++) {
            ulonglong2 wv = w[i];
            asm("fma.rn.f32x2 %0, %1, %2, %0;" : "+l"(acc[i].x) : "l"(f2), "l"(wv.x));
            asm("fma.rn.f32x2 %0, %1, %2, %0;" : "+l"(acc[i].y) : "l"(f2), "l"(wv.y));
        }
    }
}

// half gemv: acc[4] += x @ W[:, 16h:16h+16]
__device__ __forceinline__ void gemv32h(const float4* __restrict__ sW,
                                        const float4* xr, ulonglong2* acc, int h) {
#pragma unroll
    for (int k = 0; k < 32; k++) {
        float f = COMP(xr[k >> 2], k & 3);
        unsigned long long f2;
        asm("mov.b64 %0, {%1, %1};" : "=l"(f2) : "f"(f));
        const ulonglong2* w = (const ulonglong2*)(sW + k * 8 + h * 4);
#pragma unroll
        for (int i = 0; i < 4; i++) {
            ulonglong2 wv = w[i];
            asm("fma.rn.f32x2 %0, %1, %2, %0;" : "+l"(acc[i].x) : "l"(f2), "l"(wv.x));
            asm("fma.rn.f32x2 %0, %1, %2, %0;" : "+l"(acc[i].y) : "l"(f2), "l"(wv.y));
        }
    }
}

// ---------------- software grid barrier ----------------
__device__ __forceinline__ void gbar(int nb) {
    __syncthreads();
    if (threadIdx.x == 0) {
        int* cnt = &g_zero[N_NODES];
        int* gen = &g_zero[N_NODES + 1];
        int g = atomicAdd(gen, 0);
        __threadfence();
        if (atomicAdd(cnt, 1) == nb - 1) {
            *cnt = 0;
            __threadfence();
            atomicExch(gen, g + 1);
        } else {
            while (atomicAdd(gen, 0) == g) { __nanosleep(64); }
        }
        __threadfence();
    }
    __syncthreads();
}

// ---------------- persistent CSR build (self-zeroing hist) ----------------
__global__ void __launch_bounds__(CSR_T) csr_kernel(const void* ei, const float* __restrict__ pos) {
    __shared__ int s_i64;
    __shared__ int s_scan[CSR_T];
    int t = threadIdx.x;
    int b = blockIdx.x;
    int nb = gridDim.x;
    int gtid = b * CSR_T + t;
    int gsz = nb * CSR_T;

    if (t < 32) {
        int v = ((const int*)ei)[2 * t + 1];
        unsigned m = __ballot_sync(0xffffffffu, v != 0);
        if (t == 0) s_i64 = (m == 0);
    }
    __syncthreads();
    int i64 = s_i64;

    // phase 0: zero hist (barrier words untouched; gen is monotonic across replays)
    for (int n = gtid; n < N_NODES; n += gsz) g_zero[n] = 0;
    gbar(nb);

    // phase 1: pos pack + decode stash + dst histogram
    for (int n = gtid; n < N_NODES; n += gsz)
        g_pos4[n] = make_float4(pos[n * 3 + 0], pos[n * 3 + 1], pos[n * 3 + 2], 0.f);
    for (int e = gtid; e < N_EDGES; e += gsz) {
        int src, dst;
        if (i64) {
            const long long* p = (const long long*)ei;
            src = (int)p[e]; dst = (int)p[N_EDGES + e];
        } else {
            const int* p = (const int*)ei;
            src = p[e]; dst = p[N_EDGES + e];
        }
        g_tmp[e] = make_int2(src, dst);
        atomicAdd(&g_zero[dst], 1);
    }
    gbar(nb);

    // phase 2: block-local scan
    int CH = (((N_NODES + nb - 1) / nb) + 1) & ~1;
    int base = b * CH;
    int idx0 = base + 2 * t;
    int idx1 = idx0 + 1;
    int lim = min(base + CH, N_NODES);
    int v0 = (idx0 < lim) ? g_zero[idx0] : 0;
    int v1 = (idx1 < lim) ? g_zero[idx1] : 0;
    int pairsum = v0 + v1;
    s_scan[t] = pairsum;
    __syncthreads();
#pragma unroll
    for (int off = 1; off < CSR_T; off <<= 1) {
        int tt = (t >= off) ? s_scan[t - off] : 0;
        __syncthreads();
        s_scan[t] += tt;
        __syncthreads();
    }
    int texcl = s_scan[t] - pairsum;
    if (t == CSR_T - 1) g_part[b] = s_scan[CSR_T - 1];
    gbar(nb);

    // phase 3: block 0 scans block partials
    if (b == 0) {
        int pv = (t < nb) ? g_part[t] : 0;
        s_scan[t] = pv;
        __syncthreads();
#pragma unroll
        for (int off = 1; off < CSR_T; off <<= 1) {
            int tt = (t >= off) ? s_scan[t - off] : 0;
            __syncthreads();
            s_scan[t] += tt;
            __syncthreads();
        }
        if (t < nb) g_part[t] = s_scan[t] - pv;
    }
    gbar(nb);

    // phase 4: offsets + cursors
    {
        int pbase = g_part[b];
        if (idx0 < lim) { int o = pbase + texcl;      g_off[idx0] = o; g_cur[idx0] = o; }
        if (idx1 < lim) { int o = pbase + texcl + v0; g_off[idx1] = o; g_cur[idx1] = o; }
    }
    gbar(nb);

    // phase 5: scatter
    for (int e = gtid; e < N_EDGES; e += gsz) {
        int2 sd = g_tmp[e];
        float4 pd = __ldg(&g_pos4[sd.y]);
        float4 ps = __ldg(&g_pos4[sd.x]);
        float dx = pd.x - ps.x, dy = pd.y - ps.y, dz = pd.z - ps.z;
        float dist = sqrtf(dx * dx + dy * dy + dz * dz);
        int p = atomicAdd(&g_cur[sd.y], 1);
        g_epack[p] = make_int2(sd.x * 8, __float_as_int(dist));
    }
}

// ---------------- precompute folded matrices ----------------
__global__ void __launch_bounds__(256) precompute_kernel(
    const float* __restrict__ enc_w2, const float* __restrict__ enc_b2,
    const float* __restrict__ msg_w1, const float* __restrict__ msg_b1,
    const float* __restrict__ msg_w2, const float* __restrict__ msg_b2,
    const float* __restrict__ upd_w1, const float* __restrict__ upd_b1,
    const float* __restrict__ upd_w2, const float* __restrict__ upd_b2,
    const float* __restrict__ out_w, const float* __restrict__ out_b) {
    int b = blockIdx.x;
    int t = threadIdx.x;
    if (b < 13) {
        int l = (b < 12) ? (b % 3) : 2;
        int kind = (b < 12) ? (b / 3) : 4;
        const float* Wp = (l == 0) ? enc_w2 : upd_w2 + (size_t)(l - 1) * 1024;
        const float* L; const float* R; float* P;
        switch (kind) {
            case 0: L = Wp;                      R = msg_w1 + (size_t)l * 2080;        P = c_Pa[l]; break;
            case 1: L = Wp;                      R = msg_w1 + (size_t)l * 2080 + 1024; P = c_Pb[l]; break;
            case 2: L = Wp;                      R = upd_w1 + (size_t)l * 2048;        P = c_P1[l]; break;
            case 3: L = msg_w2 + (size_t)l*1024; R = upd_w1 + (size_t)l * 2048 + 1024; P = c_P2[l]; break;
            default: L = upd_w2 + 2048;          R = out_w;                            P = c_Po;    break;
        }
        for (int e = t; e < 1024; e += 256) {
            int i = e >> 5, j = e & 31;
            float s = 0.f;
            for (int k = 0; k < 32; k++) s = fmaf(L[i * 32 + k], R[k * 32 + j], s);
            P[e] = s;
        }
    } else {
        for (int e = t; e < 416; e += 256) {
            int vid = e >> 5, j = e & 31;
            int l = vid % 3;
            const float* cp = (l == 0) ? enc_b2 : upd_b2 + (size_t)(l - 1) * 32;
            float s = 0.f;
            if (vid < 3) {
                const float* R = msg_w1 + (size_t)l * 2080;
                for (int k = 0; k < 32; k++) s = fmaf(cp[k], R[k * 32 + j], s);
                c_qa[l][j] = s;
            } else if (vid < 6) {
                const float* R = msg_w1 + (size_t)l * 2080 + 1024;
                for (int k = 0; k < 32; k++) s = fmaf(cp[k], R[k * 32 + j], s);
                c_qb[l][j] = s;
            } else if (vid < 9) {
                const float* R = upd_w1 + (size_t)l * 2048;
                for (int k = 0; k < 32; k++) s = fmaf(cp[k], R[k * 32 + j], s);
                c_q1[l][j] = s + upd_b1[l * 32 + j];
            } else if (vid < 12) {
                const float* R = upd_w1 + (size_t)l * 2048 + 1024;
                const float* mb = msg_b2 + (size_t)l * 32;
                for (int k = 0; k < 32; k++) s = fmaf(mb[k], R[k * 32 + j], s);
                c_v[l][j] = s;
            } else {
                const float* ub = upd_b2 + 2 * 32;
                for (int k = 0; k < 32; k++) s = fmaf(ub[k], out_w[k * 32 + j], s);
                c_qo[j] = s + out_b[j];
            }
        }
    }
}

// ---------------- encoder ----------------
__global__ void __launch_bounds__(128) encoder_kernel(
    const float* __restrict__ feat,
    const float* __restrict__ w1, const float* __restrict__ b1) {
    __shared__ float  s_feat[128 * 33];
    __shared__ float4 s_w1[64 * 8];
    __shared__ float4 s_pa[256], s_pb[256];
    __shared__ float4 s_b1[8], s_qa[8], s_qb[8];
    for (int i = threadIdx.x; i < 512; i += 128) s_w1[i] = ((const float4*)w1)[i];
    for (int i = threadIdx.x; i < 256; i += 128) {
        s_pa[i] = ((const float4*)c_Pa[0])[i];
        s_pb[i] = ((const float4*)c_Pb[0])[i];
    }
    if (threadIdx.x < 8) {
        s_b1[threadIdx.x] = ((const float4*)b1)[threadIdx.x];
        s_qa[threadIdx.x] = ((const float4*)c_qa[0])[threadIdx.x];
        s_qb[threadIdx.x] = ((const float4*)c_qb[0])[threadIdx.x];
    }
    __syncthreads();
    int base = blockIdx.x * 128;
    int n = base + threadIdx.x;
    bool act = (n < N_NODES);

    ulonglong2 hacc[8];
#pragma unroll
    for (int i = 0; i < 8; i++) hacc[i] = pack4(s_b1[i]);

#pragma unroll
    for (int half = 0; half < 2; half++) {
        for (int j = threadIdx.x; j < 128 * 32; j += 128) {
            int r = j >> 5, col = j & 31;
            int nn = base + r;
            s_feat[r * 33 + col] =
                (nn < N_NODES) ? feat[(size_t)nn * 64 + half * 32 + col] : 0.f;
        }
        __syncthreads();
        const float* frow = &s_feat[threadIdx.x * 33];
#pragma unroll 8
        for (int k = 0; k < 32; k++) {
            float f = frow[k];
            unsigned long long f2;
            asm("mov.b64 %0, {%1, %1};" : "=l"(f2) : "f"(f));
            const ulonglong2* w = (const ulonglong2*)(s_w1 + (half * 32 + k) * 8);
#pragma unroll
            for (int i = 0; i < 8; i++) {
                ulonglong2 wv = w[i];
                asm("fma.rn.f32x2 %0, %1, %2, %0;" : "+l"(hacc[i].x) : "l"(f2), "l"(wv.x));
                asm("fma.rn.f32x2 %0, %1, %2, %0;" : "+l"(hacc[i].y) : "l"(f2), "l"(wv.y));
            }
        }
        __syncthreads();
    }
    float4 h[8];
#pragma unroll
    for (int i = 0; i < 8; i++) h[i] = relu4(unpack4(hacc[i]));

    ulonglong2 a[8], b[8];
#pragma unroll
    for (int i = 0; i < 8; i++) { a[i] = pack4(s_qa[i]); b[i] = pack4(s_qb[i]); }
    gemv32(s_pa, h, a);
    gemv32(s_pb, h, b);

    if (act) {
        ulonglong2* ph = (ulonglong2*)&g_h[(size_t)n * 8];
        ulonglong2* pa = (ulonglong2*)&g_A[(size_t)n * 8];
#pragma unroll
        for (int i = 0; i < 8; i++) {
            ph[i] = pack4(h[i]);
            pa[i] = a[i];
            g_Bh[(size_t)n * 8 + i] = f4_to_h4(unpack4(b[i]));
        }
    }
}

// ---------------- per layer agg: 64-thread blocks (tail balance), paired int4 epack loads ----------------
__global__ void __launch_bounds__(64) agg_kernel(
    const float* __restrict__ w1c, const float* __restrict__ b1) {
    int warp = (blockIdx.x * 64 + threadIdx.x) >> 5;
    int lane = threadIdx.x & 31;
    int c = lane & 7;
    int n = warp * 4 + (lane >> 3);
    bool act = (n < N_NODES);

    float4 cv = __ldg(((const float4*)w1c) + c);
    float4 bb = __ldg(((const float4*)b1) + c);

    int start = 0, deg = 0;
    if (act) {
        start = __ldg(&g_off[n]);
        deg   = __ldg(&g_zero[n]);   // hist
    }
    float4 ab = make_float4(0.f, 0.f, 0.f, 0.f);
    if (act) ab = add4(g_A[(size_t)n * 8 + c], bb);
    const unsigned long long* Bc = g_Bh + c;

    float4 acc0 = make_float4(0.f, 0.f, 0.f, 0.f);
    float4 acc1 = make_float4(0.f, 0.f, 0.f, 0.f);
    int i = 0;
    // peel one edge if start is odd so int4 loads are 16B-aligned
    if ((start & 1) && deg > 0) {
        int2 sd = __ldg(&g_epack[start]);
        float4 b = h4_to_f4(__ldg(Bc + sd.x));
        acc0 = add4(acc0, relu4(fma4(__int_as_float(sd.y), cv, add4(ab, b))));
        i = 1;
    }
    for (; i + 1 < deg; i += 2) {
        int4 sd2 = __ldg((const int4*)(g_epack + start + i));
        float4 b0 = h4_to_f4(__ldg(Bc + sd2.x));
        float4 b1v = h4_to_f4(__ldg(Bc + sd2.z));
        acc0 = add4(acc0, relu4(fma4(__int_as_float(sd2.y), cv, add4(ab, b0))));
        acc1 = add4(acc1, relu4(fma4(__int_as_float(sd2.w), cv, add4(ab, b1v))));
    }
    if (i < deg) {
        int2 sd = __ldg(&g_epack[start + i]);
        float4 b = h4_to_f4(__ldg(Bc + sd.x));
        acc0 = add4(acc0, relu4(fma4(__int_as_float(sd.y), cv, add4(ab, b))));
    }
    if (act) g_agg[(size_t)n * 8 + c] = add4(acc0, acc1);
}

// ---------------- per layer update: 2 threads per node (column halves) ----------------
__global__ void __launch_bounds__(256) update_kernel(int l, int last, float* __restrict__ outp) {
    __shared__ float4 s_p1[256], s_p2[256], s_pc[256], s_pd[256];
    __shared__ float4 s_q1[8], s_v[8], s_qc[8], s_qd[8];
    {
        const float* P1 = c_P1[l];
        const float* P2 = c_P2[l];
        const float* Pc = last ? c_Po : c_Pa[l + 1 < 3 ? l + 1 : 0];
        const float* Pd = last ? c_Po : c_Pb[l + 1 < 3 ? l + 1 : 0];
        for (int i = threadIdx.x; i < 256; i += 256) {
            s_p1[i] = ((const float4*)P1)[i];
            s_p2[i] = ((const float4*)P2)[i];
            s_pc[i] = ((const float4*)Pc)[i];
            s_pd[i] = ((const float4*)Pd)[i];
        }
        if (threadIdx.x < 8) {
            s_q1[threadIdx.x] = ((const float4*)c_q1[l])[threadIdx.x];
            s_v[threadIdx.x]  = ((const float4*)c_v[l])[threadIdx.x];
            const float* qc = last ? c_qo : c_qa[l + 1 < 3 ? l + 1 : 0];
            const float* qd = last ? c_qo : c_qb[l + 1 < 3 ? l + 1 : 0];
            s_qc[threadIdx.x] = ((const float4*)qc)[threadIdx.x];
            s_qd[threadIdx.x] = ((const float4*)qd)[threadIdx.x];
        }
    }
    __syncthreads();
    int gt = blockIdx.x * 256 + threadIdx.x;
    int n = gt >> 1;
    int h = gt & 1;
    if (n >= N_NODES) return;

    float deg = (float)g_zero[n];
    ulonglong2 uacc[4];
#pragma unroll
    for (int i = 0; i < 4; i++) {
        float4 q = s_q1[4 * h + i], vv = s_v[4 * h + i];
        uacc[i] = pack4(make_float4(fmaf(deg, vv.x, q.x), fmaf(deg, vv.y, q.y),
                                    fmaf(deg, vv.z, q.z), fmaf(deg, vv.w, q.w)));
    }
    float4 hr[8];
#pragma unroll
    for (int i = 0; i < 8; i++) hr[i] = g_h[(size_t)n * 8 + i];
    gemv32h(s_p1, hr, uacc, h);
    float4 ar[8];
#pragma unroll
    for (int i = 0; i < 8; i++) ar[i] = g_agg[(size_t)n * 8 + i];
    gemv32h(s_p2, ar, uacc, h);

    float4 uh[4];
#pragma unroll
    for (int i = 0; i < 4; i++) uh[i] = relu4(unpack4(uacc[i]));

    float4 u[8];
#pragma unroll
    for (int i = 0; i < 4; i++) {
        u[4 * h + i] = uh[i];
        float4 o;
        o.x = __shfl_xor_sync(0xffffffffu, uh[i].x, 1);
        o.y = __shfl_xor_sync(0xffffffffu, uh[i].y, 1);
        o.z = __shfl_xor_sync(0xffffffffu, uh[i].z, 1);
        o.w = __shfl_xor_sync(0xffffffffu, uh[i].w, 1);
        u[4 * (1 - h) + i] = o;
    }

    ulonglong2 cacc[4];
#pragma unroll
    for (int i = 0; i < 4; i++) cacc[i] = pack4(s_qc[4 * h + i]);
    gemv32h(s_pc, u, cacc, h);

    if (!last) {
        ulonglong2 dacc[4];
#pragma unroll
        for (int i = 0; i < 4; i++) dacc[i] = pack4(s_qd[4 * h + i]);
        gemv32h(s_pd, u, dacc, h);
        ulonglong2* ph = (ulonglong2*)&g_h[(size_t)n * 8];
        ulonglong2* pa = (ulonglong2*)&g_A[(size_t)n * 8];
#pragma unroll
        for (int i = 0; i < 4; i++) {
            ph[4 * h + i] = pack4(uh[i]);
            pa[4 * h + i] = cacc[i];
            g_Bh[(size_t)n * 8 + 4 * h + i] = f4_to_h4(unpack4(dacc[i]));
        }
    } else {
        ulonglong2* orow = (ulonglong2*)(outp + (size_t)n * 32);
#pragma unroll
        for (int i = 0; i < 4; i++) orow[4 * h + i] = cacc[i];
    }
}

// ---------------- launch ----------------
extern "C" void kernel_launch(void* const* d_in, const int* in_sizes, int n_in,
                              void* d_out, int out_size) {
    const float* node_feat = (const float*)d_in[0];
    const float* pos       = (const float*)d_in[1];
    const void*  ei        = d_in[2];
    const float* enc_w1    = (const float*)d_in[3];
    const float* enc_b1    = (const float*)d_in[4];
    const float* enc_w2    = (const float*)d_in[5];
    const float* enc_b2    = (const float*)d_in[6];
    const float* msg_w1    = (const float*)d_in[7];
    const float* msg_b1    = (const float*)d_in[8];
    const float* msg_w2    = (const float*)d_in[9];
    const float* msg_b2    = (const float*)d_in[10];
    const float* upd_w1    = (const float*)d_in[11];
    const float* upd_b1    = (const float*)d_in[12];
    const float* upd_w2    = (const float*)d_in[13];
    const float* upd_b2    = (const float*)d_in[14];
    const float* out_w     = (const float*)d_in[15];
    const float* out_b     = (const float*)d_in[16];
    float* out = (float*)d_out;

    const int NODE_BLOCKS = (N_NODES + 127) / 128;
    const int UPD_BLOCKS  = (2 * N_NODES + 255) / 256;
    const int AGG_BLOCKS  = (((N_NODES + 3) / 4) * 32 + 63) / 64;

    int nsm = 0, occ = 0;
    cudaDeviceGetAttribute(&nsm, cudaDevAttrMultiProcessorCount, 0);
    cudaOccupancyMaxActiveBlocksPerMultiprocessor(&occ, csr_kernel, CSR_T, 0);
    if (occ < 1) occ = 1;
    int csr_blocks = occ * nsm;
    if (csr_blocks > nsm) csr_blocks = nsm;
    if (csr_blocks > 512) csr_blocks = 512;

    cudaStream_t s1;
    cudaStreamCreateWithFlags(&s1, cudaStreamNonBlocking);
    cudaEvent_t ev_fork, ev_join;
    cudaEventCreateWithFlags(&ev_fork, cudaEventDisableTiming);
    cudaEventCreateWithFlags(&ev_join, cudaEventDisableTiming);

    cudaEventRecord(ev_fork, 0);
    cudaStreamWaitEvent(s1, ev_fork, 0);

    csr_kernel<<<csr_blocks, CSR_T>>>(ei, pos);                        // kernel #1

    precompute_kernel<<<14, 256, 0, s1>>>(enc_w2, enc_b2, msg_w1, msg_b1, msg_w2, msg_b2,
                                          upd_w1, upd_b1, upd_w2, upd_b2, out_w, out_b); // #2
    encoder_kernel<<<NODE_BLOCKS, 128, 0, s1>>>(node_feat, enc_w1, enc_b1);              // #3
    cudaEventRecord(ev_join, s1);

    cudaStreamWaitEvent(0, ev_join, 0);

    for (int l = 0; l < 3; l++) {
        const float* w1 = msg_w1 + (size_t)l * 65 * 32;
        agg_kernel<<<AGG_BLOCKS, 64>>>(w1 + 64 * 32, msg_b1 + (size_t)l * 32);  // l=0 -> #4 (profiled)
        update_kernel<<<UPD_BLOCKS, 256>>>(l, l == 2, out);
    }
}